// round 1
// baseline (speedup 1.0000x reference)
#include <cuda_runtime.h>
#include <math.h>

// ---------------- problem constants ----------------
#define DD     512
#define SS     2048
#define BATCH  8
#define VIEWS  2
#define VB     16               // VIEWS*BATCH
#define NTOK   32768            // VB*SS
#define NVOCAB 8192
#define NSTEPS 16
#define DECAYF 0.999f
#define EPSF   1e-6f

// ---------------- scratch (static device globals; allocation-free) ----------------
__device__ float g_state[(size_t)NTOK * DD];          // 64 MB
__device__ float g_n    [(size_t)NTOK * DD];          // 64 MB
__device__ float g_big  [(size_t)NTOK * 1536];        // 192 MB (GU then QKV)
__device__ float g_acc  [(size_t)VB * DD * DD];       // 16 MB
__device__ float g_accWo[(size_t)VB * DD * DD];       // 16 MB
__device__ float g_cmb  [(size_t)BATCH * SS * DD];    // 32 MB
__device__ float g_Wgu  [(size_t)DD * 1536];
__device__ float g_Wqkv [(size_t)DD * 1536];

// ---------------- tiled fp32 GEMM ----------------
#define BM 128
#define BN 128
#define BKT 16
#define TM 8
#define TN 8

enum { EPI_STORE = 0, EPI_GATED = 1, EPI_BETA = 2, EPI_ADD = 3 };

// C(MxN) = epi( alpha * A(MxK,row-major,lda) * B(KxN,row-major,ldb) )
// batched via blockIdx.z with element strides sA/sB/sC/sG.
template <int EPI>
__global__ void __launch_bounds__(256) sgemm_nn(
    int M, int N, int K,
    const float* __restrict__ A, int lda, size_t sA,
    const float* __restrict__ B, int ldb, size_t sB,
    float* __restrict__ C, int ldc, size_t sC,
    float alpha, float beta,
    const float* __restrict__ G, int ldg, size_t sG)
{
    A += (size_t)blockIdx.z * sA;
    B += (size_t)blockIdx.z * sB;
    C += (size_t)blockIdx.z * sC;
    if (EPI == EPI_GATED) G += (size_t)blockIdx.z * sG;

    __shared__ float As[BKT][BM];
    __shared__ float Bs[BKT][BN];

    const int tid  = threadIdx.x;
    const int tCol = tid & 15;     // 0..15
    const int tRow = tid >> 4;     // 0..15

    const int aRow = tid >> 2;           // 0..63
    const int aCol = (tid & 3) << 2;     // 0,4,8,12
    const int bRow = tid >> 5;           // 0..7
    const int bCol = (tid & 31) << 2;    // 0..124

    const float* Ab = A + (size_t)blockIdx.y * BM * lda;
    const float* Bb = B + (size_t)blockIdx.x * BN;

    float acc[TM][TN];
#pragma unroll
    for (int i = 0; i < TM; i++)
#pragma unroll
        for (int j = 0; j < TN; j++) acc[i][j] = 0.f;

    for (int k0 = 0; k0 < K; k0 += BKT) {
#pragma unroll
        for (int i = 0; i < 2; i++) {
            float4 v = *reinterpret_cast<const float4*>(
                Ab + (size_t)(aRow + i * 64) * lda + k0 + aCol);
            As[aCol + 0][aRow + i * 64] = v.x;
            As[aCol + 1][aRow + i * 64] = v.y;
            As[aCol + 2][aRow + i * 64] = v.z;
            As[aCol + 3][aRow + i * 64] = v.w;
        }
#pragma unroll
        for (int j = 0; j < 2; j++) {
            *reinterpret_cast<float4*>(&Bs[bRow + j * 8][bCol]) =
                *reinterpret_cast<const float4*>(
                    Bb + (size_t)(k0 + bRow + j * 8) * ldb + bCol);
        }
        __syncthreads();

        float regM[TM], regN[TN];
#pragma unroll
        for (int kk = 0; kk < BKT; kk++) {
#pragma unroll
            for (int i = 0; i < TM; i++) regM[i] = As[kk][tRow * TM + i];
#pragma unroll
            for (int j = 0; j < TN; j++) regN[j] = Bs[kk][tCol * TN + j];
#pragma unroll
            for (int i = 0; i < TM; i++)
#pragma unroll
                for (int j = 0; j < TN; j++)
                    acc[i][j] = fmaf(regM[i], regN[j], acc[i][j]);
        }
        __syncthreads();
    }

#pragma unroll
    for (int i = 0; i < TM; i++) {
        size_t r = (size_t)blockIdx.y * BM + tRow * TM + i;
#pragma unroll
        for (int j = 0; j < TN; j++) {
            size_t c = (size_t)blockIdx.x * BN + tCol * TN + j;
            float v = alpha * acc[i][j];
            float* cp = C + r * ldc + c;
            if (EPI == EPI_STORE)      *cp = v;
            else if (EPI == EPI_GATED) *cp += G[r * ldg + c] * v;
            else if (EPI == EPI_BETA)  *cp = beta * (*cp) + v;
            else /* EPI_ADD */         *cp += v;
        }
    }
}

// C(MxN) = beta*C + alpha * A^T * B  where A is [K x M] (A[k*lda+m]), B is [K x N].
__global__ void __launch_bounds__(256) sgemm_tn_beta(
    int M, int N, int K,
    const float* __restrict__ A, int lda, size_t sA,
    const float* __restrict__ B, int ldb, size_t sB,
    float* __restrict__ C, int ldc, size_t sC,
    float alpha, float beta)
{
    A += (size_t)blockIdx.z * sA;
    B += (size_t)blockIdx.z * sB;
    C += (size_t)blockIdx.z * sC;

    __shared__ float As[BKT][BM];
    __shared__ float Bs[BKT][BN];

    const int tid  = threadIdx.x;
    const int tCol = tid & 15;
    const int tRow = tid >> 4;

    const int ldRow = tid >> 5;          // 0..7
    const int ldCol = (tid & 31) << 2;   // 0..124

    const float* Ab = A + (size_t)blockIdx.y * BM;
    const float* Bb = B + (size_t)blockIdx.x * BN;

    float acc[TM][TN];
#pragma unroll
    for (int i = 0; i < TM; i++)
#pragma unroll
        for (int j = 0; j < TN; j++) acc[i][j] = 0.f;

    for (int k0 = 0; k0 < K; k0 += BKT) {
#pragma unroll
        for (int j = 0; j < 2; j++) {
            *reinterpret_cast<float4*>(&As[ldRow + j * 8][ldCol]) =
                *reinterpret_cast<const float4*>(
                    Ab + (size_t)(k0 + ldRow + j * 8) * lda + ldCol);
            *reinterpret_cast<float4*>(&Bs[ldRow + j * 8][ldCol]) =
                *reinterpret_cast<const float4*>(
                    Bb + (size_t)(k0 + ldRow + j * 8) * ldb + ldCol);
        }
        __syncthreads();

        float regM[TM], regN[TN];
#pragma unroll
        for (int kk = 0; kk < BKT; kk++) {
#pragma unroll
            for (int i = 0; i < TM; i++) regM[i] = As[kk][tRow * TM + i];
#pragma unroll
            for (int j = 0; j < TN; j++) regN[j] = Bs[kk][tCol * TN + j];
#pragma unroll
            for (int i = 0; i < TM; i++)
#pragma unroll
                for (int j = 0; j < TN; j++)
                    acc[i][j] = fmaf(regM[i], regN[j], acc[i][j]);
        }
        __syncthreads();
    }

#pragma unroll
    for (int i = 0; i < TM; i++) {
        size_t r = (size_t)blockIdx.y * BM + tRow * TM + i;
#pragma unroll
        for (int j = 0; j < TN; j++) {
            size_t c = (size_t)blockIdx.x * BN + tCol * TN + j;
            float* cp = C + r * ldc + c;
            *cp = beta * (*cp) + alpha * acc[i][j];
        }
    }
}

// ---------------- elementwise / norm kernels ----------------

// y[row] = rms(x[row]), row length DD=512, 128 threads * float4
__global__ void rms_kernel(const float* __restrict__ x, float* __restrict__ y)
{
    size_t row = blockIdx.x;
    int t = threadIdx.x;
    float4 v = reinterpret_cast<const float4*>(x + row * DD)[t];
    float ss = v.x * v.x + v.y * v.y + v.z * v.z + v.w * v.w;
#pragma unroll
    for (int o = 16; o > 0; o >>= 1) ss += __shfl_xor_sync(0xffffffffu, ss, o);
    __shared__ float sb[4];
    if ((t & 31) == 0) sb[t >> 5] = ss;
    __syncthreads();
    float tot = sb[0] + sb[1] + sb[2] + sb[3];
    float r = rsqrtf(tot * (1.0f / DD) + EPSF);
    float4 o4 = make_float4(v.x * r, v.y * r, v.z * r, v.w * r);
    reinterpret_cast<float4*>(y + row * DD)[t] = o4;
}

// cmb[row] = rms(0.5*(state[row] + state[row + 16384]))
__global__ void combine_rms_kernel()
{
    size_t row = blockIdx.x;
    int t = threadIdx.x;
    float4 a = reinterpret_cast<const float4*>(g_state + row * DD)[t];
    float4 b = reinterpret_cast<const float4*>(g_state + (row + (size_t)BATCH * SS) * DD)[t];
    float4 v = make_float4(0.5f * (a.x + b.x), 0.5f * (a.y + b.y),
                           0.5f * (a.z + b.z), 0.5f * (a.w + b.w));
    float ss = v.x * v.x + v.y * v.y + v.z * v.z + v.w * v.w;
#pragma unroll
    for (int o = 16; o > 0; o >>= 1) ss += __shfl_xor_sync(0xffffffffu, ss, o);
    __shared__ float sb[4];
    if ((t & 31) == 0) sb[t >> 5] = ss;
    __syncthreads();
    float tot = sb[0] + sb[1] + sb[2] + sb[3];
    float r = rsqrtf(tot * (1.0f / DD) + EPSF);
    float4 o4 = make_float4(v.x * r, v.y * r, v.z * r, v.w * r);
    reinterpret_cast<float4*>(g_cmb + row * DD)[t] = o4;
}

// state0[vb*SS+s, :] = emb[v, tok(b,s), :]
__global__ void embed_kernel(const int* __restrict__ toks, const float* __restrict__ emb)
{
    size_t row = blockIdx.x;
    int t = threadIdx.x;
    int s = (int)(row & (SS - 1));
    int vb = (int)(row >> 11);
    int b = vb & 7, v = vb >> 3;
    int tok = toks[b * SS + s];
    const float4* src = reinterpret_cast<const float4*>(
        emb + ((size_t)v * NVOCAB + tok) * DD);
    reinterpret_cast<float4*>(g_state + row * DD)[t] = src[t];
}

// pack Wgu = [Wg | Wu], Wqkv = [Wq | Wk | Wv] (row-major 512 x 1536)
__global__ void pack_kernel(const float* __restrict__ Wg, const float* __restrict__ Wu,
                            const float* __restrict__ Wq, const float* __restrict__ Wk,
                            const float* __restrict__ Wv)
{
    int idx = blockIdx.x * blockDim.x + threadIdx.x;
    if (idx >= DD * 1536) return;
    int r = idx / 1536, c = idx % 1536;
    g_Wgu[idx] = (c < DD) ? Wg[r * DD + c] : Wu[r * (2 * DD) + (c - DD)];
    float q;
    if (c < DD)            q = Wq[r * DD + c];
    else if (c < 2 * DD)   q = Wk[r * DD + (c - DD)];
    else                   q = Wv[r * DD + (c - 2 * DD)];
    g_Wqkv[idx] = q;
}

__global__ void zero_acc_kernel()
{
    size_t i = (size_t)blockIdx.x * blockDim.x + threadIdx.x;
    if (i < (size_t)VB * DD * DD) g_acc[i] = 0.f;
}

// GU activation in place: cols<512 -> sigmoid (gate); cols>=512 -> exact gelu (H)
__global__ void act_gu_kernel()
{
    size_t i = (size_t)blockIdx.x * blockDim.x + threadIdx.x;
    if (i >= (size_t)NTOK * 1536) return;
    int c = (int)(i % 1536);
    float x = g_big[i];
    if (c < DD)
        g_big[i] = 1.0f / (1.0f + expf(-x));
    else
        g_big[i] = 0.5f * x * (1.0f + erff(x * 0.70710678118654752f));
}

// phi = elu(x)+1 on QKV cols [0,1024) in place (q and k); v untouched
__global__ void act_phi_kernel()
{
    size_t i = (size_t)blockIdx.x * blockDim.x + threadIdx.x;
    if (i >= (size_t)NTOK * 1024) return;
    size_t row = i >> 10;
    int c = (int)(i & 1023);
    size_t idx = row * 1536 + c;
    float x = g_big[idx];
    g_big[idx] = (x > 0.f) ? x + 1.f : expf(x);
}

// ---------------- host launch ----------------
static float* sym_addr(const void* sym)
{
    void* p = nullptr;
    cudaGetSymbolAddress(&p, sym);
    return (float*)p;
}

extern "C" void kernel_launch(void* const* d_in, const int* in_sizes, int n_in,
                              void* d_out, int out_size)
{
    const int*   toks = (const int*)d_in[0];
    const float* emb  = (const float*)d_in[1];
    const float* Wg   = (const float*)d_in[2];
    const float* Wu   = (const float*)d_in[3];
    const float* Wd   = (const float*)d_in[4];
    const float* Wq   = (const float*)d_in[5];
    const float* Wk   = (const float*)d_in[6];
    const float* Wv   = (const float*)d_in[7];
    const float* Wo   = (const float*)d_in[8];
    const float* Wlm  = (const float*)d_in[9];
    float* out = (float*)d_out;

    float* state = sym_addr(g_state);
    float* nbuf  = sym_addr(g_n);
    float* big   = sym_addr(g_big);
    float* acc   = sym_addr(g_acc);
    float* accWo = sym_addr(g_accWo);
    float* cmb   = sym_addr(g_cmb);
    float* wgu   = sym_addr(g_Wgu);
    float* wqkv  = sym_addr(g_Wqkv);

    const float inv_s      = 1.0f / (float)SS;
    const float inv_sqrt_d = 1.0f / sqrtf((float)DD);
    const size_t qkv_bstride = (size_t)SS * 1536;
    const size_t acc_bstride = (size_t)DD * DD;
    const size_t st_bstride  = (size_t)SS * DD;

    // setup
    embed_kernel<<<NTOK, 128>>>(toks, emb);
    pack_kernel<<<(DD * 1536 + 255) / 256, 256>>>(Wg, Wu, Wq, Wk, Wv);
    zero_acc_kernel<<<((int)((size_t)VB * DD * DD) + 255) / 256, 256>>>();

    const size_t gu_elems  = (size_t)NTOK * 1536;
    const size_t phi_elems = (size_t)NTOK * 1024;

    for (int step = 0; step < NSTEPS; step++) {
        // n = rms(state)
        rms_kernel<<<NTOK, 128>>>(state, nbuf);
        // GU = n @ [Wg|Wu]   (32768 x 1536)
        sgemm_nn<EPI_STORE><<<dim3(1536 / BN, NTOK / BM, 1), 256>>>(
            NTOK, 1536, DD, nbuf, DD, 0, wgu, 1536, 0, big, 1536, 0,
            1.f, 0.f, nullptr, 0, 0);
        // gate = sigmoid(GU[:, :512]); H = gelu(GU[:, 512:]) (in place)
        act_gu_kernel<<<(unsigned)((gu_elems + 255) / 256), 256>>>();
        // state += gate * (H @ Wd)
        sgemm_nn<EPI_GATED><<<dim3(DD / BN, NTOK / BM, 1), 256>>>(
            NTOK, DD, 2 * DD, big + DD, 1536, 0, Wd, DD, 0, state, DD, 0,
            1.f, 0.f, big, 1536, 0);
        // n2 = rms(state)
        rms_kernel<<<NTOK, 128>>>(state, nbuf);
        // QKV = n2 @ [Wq|Wk|Wv]
        sgemm_nn<EPI_STORE><<<dim3(1536 / BN, NTOK / BM, 1), 256>>>(
            NTOK, 1536, DD, nbuf, DD, 0, wqkv, 1536, 0, big, 1536, 0,
            1.f, 0.f, nullptr, 0, 0);
        // q,k <- phi
        act_phi_kernel<<<(unsigned)((phi_elems + 255) / 256), 256>>>();
        // acc = DECAY*acc + inv_s * k^T @ v   (batched, 16)
        sgemm_tn_beta<<<dim3(DD / BN, DD / BM, VB), 256>>>(
            DD, DD, SS,
            big + DD, 1536, qkv_bstride,
            big + 2 * DD, 1536, qkv_bstride,
            acc, DD, acc_bstride, inv_s, DECAYF);
        // accWo = acc @ Wo (batched)
        sgemm_nn<EPI_STORE><<<dim3(DD / BN, DD / BM, VB), 256>>>(
            DD, DD, DD, acc, DD, acc_bstride, Wo, DD, 0,
            accWo, DD, acc_bstride, 1.f, 0.f, nullptr, 0, 0);
        // state += inv_sqrt_d * q @ accWo (batched over views*batch)
        sgemm_nn<EPI_ADD><<<dim3(DD / BN, SS / BM, VB), 256>>>(
            SS, DD, DD, big, 1536, qkv_bstride, accWo, DD, acc_bstride,
            state, DD, st_bstride, inv_sqrt_d, 0.f, nullptr, 0, 0);
    }

    // combined = mean over views, rms-normalized
    combine_rms_kernel<<<BATCH * SS, 128>>>();
    // logits = cmb @ Wlm  (16384 x 8192)
    sgemm_nn<EPI_STORE><<<dim3(NVOCAB / BN, (BATCH * SS) / BM, 1), 256>>>(
        BATCH * SS, NVOCAB, DD, cmb, DD, 0, Wlm, NVOCAB, 0, out, NVOCAB, 0,
        1.f, 0.f, nullptr, 0, 0);
    (void)in_sizes; (void)n_in; (void)out_size;
}

// round 2
// speedup vs baseline: 1.6172x; 1.6172x over previous
#include <cuda_runtime.h>
#include <cuda_bf16.h>
#include <math.h>
#include <stdint.h>

// ---------------- problem constants ----------------
#define DD     512
#define SS     2048
#define BATCH  8
#define VIEWS  2
#define VB     16               // VIEWS*BATCH
#define NTOK   32768            // VB*SS
#define NVOCAB 8192
#define NSTEPS 16
#define DECAYF 0.999f
#define EPSF   1e-6f

// ---------------- scratch (static device globals; allocation-free) ----------------
__device__ float g_state[(size_t)NTOK * DD];          // 64 MB
__device__ float g_n    [(size_t)NTOK * DD];          // 64 MB
__device__ float g_big  [(size_t)NTOK * 1536];        // 192 MB (GU then QKV)
__device__ float g_acc  [(size_t)VB * DD * DD];       // 16 MB
__device__ float g_accWo[(size_t)VB * DD * DD];       // 16 MB
__device__ float g_cmb  [(size_t)BATCH * SS * DD];    // 32 MB
__device__ float g_Wgu  [(size_t)DD * 1536];
__device__ float g_Wqkv [(size_t)DD * 1536];

// ---------------- tensor-core GEMM (bf16x3 = fp32-accurate) ----------------
// C(MxN) = epi( alpha * op(A) * B )
//   op(A) = A           (TRANSA=false, A row-major [M x K], leading dim lda)
//   op(A) = A^T         (TRANSA=true,  A row-major [K x M], leading dim lda)
//   B row-major [K x N], leading dim ldb.
// Each fp32 operand is split into hi+lo bf16; product computed as
//   Ahi*Bhi + Ahi*Blo + Alo*Bhi  (error ~2^-17).

enum { EPI_STORE = 0, EPI_GATED = 1, EPI_BETA = 2, EPI_ADD = 3 };

#define GBM 128
#define GBN 128
#define GBK 32
#define A_STRIDE 40    // bf16 elems per smem A row (32 + 8 pad -> 80B)
#define B_STRIDE 136   // bf16 elems per smem B row (128 + 8 pad -> 272B)

__device__ __forceinline__ uint32_t bf2pack(float x, float y)
{
    __nv_bfloat162 t = __floats2bfloat162_rn(x, y);
    return reinterpret_cast<uint32_t&>(t);
}
__device__ __forceinline__ float bfround(float x)
{
    return __bfloat162float(__float2bfloat16_rn(x));
}
__device__ __forceinline__ uint16_t bf1(float x)
{
    __nv_bfloat16 b = __float2bfloat16_rn(x);
    return reinterpret_cast<uint16_t&>(b);
}

__device__ __forceinline__ void ldsm4(uint32_t r[4], const void* p)
{
    uint32_t a = (uint32_t)__cvta_generic_to_shared(p);
    asm volatile("ldmatrix.sync.aligned.m8n8.x4.shared.b16 {%0,%1,%2,%3}, [%4];"
                 : "=r"(r[0]), "=r"(r[1]), "=r"(r[2]), "=r"(r[3]) : "r"(a));
}
__device__ __forceinline__ void ldsm4t(uint32_t r[4], const void* p)
{
    uint32_t a = (uint32_t)__cvta_generic_to_shared(p);
    asm volatile("ldmatrix.sync.aligned.m8n8.x4.trans.shared.b16 {%0,%1,%2,%3}, [%4];"
                 : "=r"(r[0]), "=r"(r[1]), "=r"(r[2]), "=r"(r[3]) : "r"(a));
}
__device__ __forceinline__ void mma16816(float c[4], const uint32_t a[4], const uint32_t b[2])
{
    asm volatile(
        "mma.sync.aligned.m16n8k16.row.col.f32.bf16.bf16.f32 "
        "{%0,%1,%2,%3}, {%4,%5,%6,%7}, {%8,%9}, {%0,%1,%2,%3};"
        : "+f"(c[0]), "+f"(c[1]), "+f"(c[2]), "+f"(c[3])
        : "r"(a[0]), "r"(a[1]), "r"(a[2]), "r"(a[3]), "r"(b[0]), "r"(b[1]));
}

template <int EPI, bool TRANSA>
__global__ void __launch_bounds__(256) mma_gemm(
    int M, int N, int K,
    const float* __restrict__ A, int lda, size_t strA,
    const float* __restrict__ B, int ldb, size_t strB,
    float* __restrict__ C, int ldc, size_t strC,
    float alpha, float beta,
    const float* __restrict__ G, int ldg, size_t strG)
{
    A += (size_t)blockIdx.z * strA;
    B += (size_t)blockIdx.z * strB;
    C += (size_t)blockIdx.z * strC;
    if (EPI == EPI_GATED) G += (size_t)blockIdx.z * strG;

    __shared__ __align__(16) uint16_t sA[2][GBM][A_STRIDE]; // [hi/lo][m][k]
    __shared__ __align__(16) uint16_t sB[2][GBK][B_STRIDE]; // [hi/lo][k][n]

    const int tid  = threadIdx.x;
    const int lane = tid & 31;
    const int warp = tid >> 5;
    const int wm   = warp & 3;   // 4 warps along M (32 rows each)
    const int wn   = warp >> 2;  // 2 warps along N (64 cols each)

    const size_t m_blk = (size_t)blockIdx.y * GBM;
    const size_t n_blk = (size_t)blockIdx.x * GBN;

    float acc[2][8][4];
#pragma unroll
    for (int mi = 0; mi < 2; mi++)
#pragma unroll
        for (int ni = 0; ni < 8; ni++)
#pragma unroll
            for (int v = 0; v < 4; v++) acc[mi][ni][v] = 0.f;

    for (int k0 = 0; k0 < K; k0 += GBK) {
        // ---- load A tile -> smem (hi/lo bf16 split) ----
        if (!TRANSA) {
#pragma unroll
            for (int p = 0; p < 4; p++) {
                int idx = tid + p * 256;
                int r = idx >> 3;           // 0..127
                int c = (idx & 7) * 4;      // 0..28
                float4 v = *reinterpret_cast<const float4*>(
                    A + (m_blk + r) * lda + k0 + c);
                uint32_t* dh = reinterpret_cast<uint32_t*>(&sA[0][r][c]);
                uint32_t* dl = reinterpret_cast<uint32_t*>(&sA[1][r][c]);
                dh[0] = bf2pack(v.x, v.y);
                dh[1] = bf2pack(v.z, v.w);
                dl[0] = bf2pack(v.x - bfround(v.x), v.y - bfround(v.y));
                dl[1] = bf2pack(v.z - bfround(v.z), v.w - bfround(v.w));
            }
        } else {
#pragma unroll
            for (int p = 0; p < 4; p++) {
                int idx = tid + p * 256;
                int kr = idx >> 5;          // 0..31
                int m4 = (idx & 31) * 4;    // 0..124
                float4 v = *reinterpret_cast<const float4*>(
                    A + (size_t)(k0 + kr) * lda + m_blk + m4);
                sA[0][m4 + 0][kr] = bf1(v.x);
                sA[0][m4 + 1][kr] = bf1(v.y);
                sA[0][m4 + 2][kr] = bf1(v.z);
                sA[0][m4 + 3][kr] = bf1(v.w);
                sA[1][m4 + 0][kr] = bf1(v.x - bfround(v.x));
                sA[1][m4 + 1][kr] = bf1(v.y - bfround(v.y));
                sA[1][m4 + 2][kr] = bf1(v.z - bfround(v.z));
                sA[1][m4 + 3][kr] = bf1(v.w - bfround(v.w));
            }
        }
        // ---- load B tile -> smem (hi/lo) ----
#pragma unroll
        for (int p = 0; p < 4; p++) {
            int idx = tid + p * 256;
            int kr = idx >> 5;              // 0..31
            int n4 = (idx & 31) * 4;        // 0..124
            float4 v = *reinterpret_cast<const float4*>(
                B + (size_t)(k0 + kr) * ldb + n_blk + n4);
            uint32_t* dh = reinterpret_cast<uint32_t*>(&sB[0][kr][n4]);
            uint32_t* dl = reinterpret_cast<uint32_t*>(&sB[1][kr][n4]);
            dh[0] = bf2pack(v.x, v.y);
            dh[1] = bf2pack(v.z, v.w);
            dl[0] = bf2pack(v.x - bfround(v.x), v.y - bfround(v.y));
            dl[1] = bf2pack(v.z - bfround(v.z), v.w - bfround(v.w));
        }
        __syncthreads();

        // ---- compute: 2 k-slices of 16 ----
#pragma unroll
        for (int ks = 0; ks < 2; ks++) {
            const int kk = ks * 16;
            uint32_t ah[2][4], al[2][4];
            const int ar = lane & 15;
            const int ac = kk + (lane >> 4) * 8;
            ldsm4(ah[0], &sA[0][wm * 32 + ar][ac]);
            ldsm4(ah[1], &sA[0][wm * 32 + 16 + ar][ac]);
            ldsm4(al[0], &sA[1][wm * 32 + ar][ac]);
            ldsm4(al[1], &sA[1][wm * 32 + 16 + ar][ac]);

            uint32_t bh[8][2], bl[8][2];
            const int q  = lane >> 3;
            const int br = kk + (q & 1) * 8 + (lane & 7);
#pragma unroll
            for (int nt = 0; nt < 4; nt++) {
                const int bc = wn * 64 + nt * 16 + (q >> 1) * 8;
                uint32_t r[4];
                ldsm4t(r, &sB[0][br][bc]);
                bh[2 * nt][0] = r[0]; bh[2 * nt][1] = r[1];
                bh[2 * nt + 1][0] = r[2]; bh[2 * nt + 1][1] = r[3];
                ldsm4t(r, &sB[1][br][bc]);
                bl[2 * nt][0] = r[0]; bl[2 * nt][1] = r[1];
                bl[2 * nt + 1][0] = r[2]; bl[2 * nt + 1][1] = r[3];
            }
#pragma unroll
            for (int mi = 0; mi < 2; mi++)
#pragma unroll
                for (int ni = 0; ni < 8; ni++) {
                    mma16816(acc[mi][ni], ah[mi], bh[ni]);
                    mma16816(acc[mi][ni], ah[mi], bl[ni]);
                    mma16816(acc[mi][ni], al[mi], bh[ni]);
                }
        }
        __syncthreads();
    }

    // ---- epilogue ----
    const int g  = lane >> 2;
    const int tg = lane & 3;
#pragma unroll
    for (int mi = 0; mi < 2; mi++) {
        size_t row0 = m_blk + wm * 32 + mi * 16 + g;
        size_t row1 = row0 + 8;
#pragma unroll
        for (int ni = 0; ni < 8; ni++) {
            size_t col = n_blk + wn * 64 + ni * 8 + tg * 2;
            float2 v0 = make_float2(alpha * acc[mi][ni][0], alpha * acc[mi][ni][1]);
            float2 v1 = make_float2(alpha * acc[mi][ni][2], alpha * acc[mi][ni][3]);
            float2* cp0 = reinterpret_cast<float2*>(C + row0 * ldc + col);
            float2* cp1 = reinterpret_cast<float2*>(C + row1 * ldc + col);
            if (EPI == EPI_STORE) {
                *cp0 = v0; *cp1 = v1;
            } else if (EPI == EPI_GATED) {
                float2 g0 = *reinterpret_cast<const float2*>(G + row0 * ldg + col);
                float2 g1 = *reinterpret_cast<const float2*>(G + row1 * ldg + col);
                float2 c0 = *cp0, c1 = *cp1;
                c0.x += g0.x * v0.x; c0.y += g0.y * v0.y;
                c1.x += g1.x * v1.x; c1.y += g1.y * v1.y;
                *cp0 = c0; *cp1 = c1;
            } else if (EPI == EPI_BETA) {
                float2 c0 = *cp0, c1 = *cp1;
                c0.x = beta * c0.x + v0.x; c0.y = beta * c0.y + v0.y;
                c1.x = beta * c1.x + v1.x; c1.y = beta * c1.y + v1.y;
                *cp0 = c0; *cp1 = c1;
            } else { // EPI_ADD
                float2 c0 = *cp0, c1 = *cp1;
                c0.x += v0.x; c0.y += v0.y;
                c1.x += v1.x; c1.y += v1.y;
                *cp0 = c0; *cp1 = c1;
            }
        }
    }
}

// ---------------- elementwise / norm kernels ----------------

__global__ void rms_kernel(const float* __restrict__ x, float* __restrict__ y)
{
    size_t row = blockIdx.x;
    int t = threadIdx.x;
    float4 v = reinterpret_cast<const float4*>(x + row * DD)[t];
    float ss = v.x * v.x + v.y * v.y + v.z * v.z + v.w * v.w;
#pragma unroll
    for (int o = 16; o > 0; o >>= 1) ss += __shfl_xor_sync(0xffffffffu, ss, o);
    __shared__ float sb[4];
    if ((t & 31) == 0) sb[t >> 5] = ss;
    __syncthreads();
    float tot = sb[0] + sb[1] + sb[2] + sb[3];
    float r = rsqrtf(tot * (1.0f / DD) + EPSF);
    float4 o4 = make_float4(v.x * r, v.y * r, v.z * r, v.w * r);
    reinterpret_cast<float4*>(y + row * DD)[t] = o4;
}

__global__ void combine_rms_kernel()
{
    size_t row = blockIdx.x;
    int t = threadIdx.x;
    float4 a = reinterpret_cast<const float4*>(g_state + row * DD)[t];
    float4 b = reinterpret_cast<const float4*>(g_state + (row + (size_t)BATCH * SS) * DD)[t];
    float4 v = make_float4(0.5f * (a.x + b.x), 0.5f * (a.y + b.y),
                           0.5f * (a.z + b.z), 0.5f * (a.w + b.w));
    float ss = v.x * v.x + v.y * v.y + v.z * v.z + v.w * v.w;
#pragma unroll
    for (int o = 16; o > 0; o >>= 1) ss += __shfl_xor_sync(0xffffffffu, ss, o);
    __shared__ float sb[4];
    if ((t & 31) == 0) sb[t >> 5] = ss;
    __syncthreads();
    float tot = sb[0] + sb[1] + sb[2] + sb[3];
    float r = rsqrtf(tot * (1.0f / DD) + EPSF);
    float4 o4 = make_float4(v.x * r, v.y * r, v.z * r, v.w * r);
    reinterpret_cast<float4*>(g_cmb + row * DD)[t] = o4;
}

__global__ void embed_kernel(const int* __restrict__ toks, const float* __restrict__ emb)
{
    size_t row = blockIdx.x;
    int t = threadIdx.x;
    int s = (int)(row & (SS - 1));
    int vb = (int)(row >> 11);
    int b = vb & 7, v = vb >> 3;
    int tok = toks[b * SS + s];
    const float4* src = reinterpret_cast<const float4*>(
        emb + ((size_t)v * NVOCAB + tok) * DD);
    reinterpret_cast<float4*>(g_state + row * DD)[t] = src[t];
}

__global__ void pack_kernel(const float* __restrict__ Wg, const float* __restrict__ Wu,
                            const float* __restrict__ Wq, const float* __restrict__ Wk,
                            const float* __restrict__ Wv)
{
    int idx = blockIdx.x * blockDim.x + threadIdx.x;
    if (idx >= DD * 1536) return;
    int r = idx / 1536, c = idx % 1536;
    g_Wgu[idx] = (c < DD) ? Wg[r * DD + c] : Wu[r * (2 * DD) + (c - DD)];
    float q;
    if (c < DD)            q = Wq[r * DD + c];
    else if (c < 2 * DD)   q = Wk[r * DD + (c - DD)];
    else                   q = Wv[r * DD + (c - 2 * DD)];
    g_Wqkv[idx] = q;
}

__global__ void zero_acc_kernel()
{
    size_t i = (size_t)blockIdx.x * blockDim.x + threadIdx.x;
    if (i < (size_t)VB * DD * DD) g_acc[i] = 0.f;
}

__global__ void act_gu_kernel()
{
    size_t i = (size_t)blockIdx.x * blockDim.x + threadIdx.x;
    if (i >= (size_t)NTOK * 1536) return;
    int c = (int)(i % 1536);
    float x = g_big[i];
    if (c < DD)
        g_big[i] = 1.0f / (1.0f + expf(-x));
    else
        g_big[i] = 0.5f * x * (1.0f + erff(x * 0.70710678118654752f));
}

__global__ void act_phi_kernel()
{
    size_t i = (size_t)blockIdx.x * blockDim.x + threadIdx.x;
    if (i >= (size_t)NTOK * 1024) return;
    size_t row = i >> 10;
    int c = (int)(i & 1023);
    size_t idx = row * 1536 + c;
    float x = g_big[idx];
    g_big[idx] = (x > 0.f) ? x + 1.f : expf(x);
}

// ---------------- host launch ----------------
static float* sym_addr(const void* sym)
{
    void* p = nullptr;
    cudaGetSymbolAddress(&p, sym);
    return (float*)p;
}

extern "C" void kernel_launch(void* const* d_in, const int* in_sizes, int n_in,
                              void* d_out, int out_size)
{
    const int*   toks = (const int*)d_in[0];
    const float* emb  = (const float*)d_in[1];
    const float* Wg   = (const float*)d_in[2];
    const float* Wu   = (const float*)d_in[3];
    const float* Wd   = (const float*)d_in[4];
    const float* Wq   = (const float*)d_in[5];
    const float* Wk   = (const float*)d_in[6];
    const float* Wv   = (const float*)d_in[7];
    const float* Wo   = (const float*)d_in[8];
    const float* Wlm  = (const float*)d_in[9];
    float* out = (float*)d_out;

    float* state = sym_addr(g_state);
    float* nbuf  = sym_addr(g_n);
    float* big   = sym_addr(g_big);
    float* acc   = sym_addr(g_acc);
    float* accWo = sym_addr(g_accWo);
    float* cmb   = sym_addr(g_cmb);
    float* wgu   = sym_addr(g_Wgu);
    float* wqkv  = sym_addr(g_Wqkv);

    const float inv_s      = 1.0f / (float)SS;
    const float inv_sqrt_d = 1.0f / sqrtf((float)DD);
    const size_t qkv_bstride = (size_t)SS * 1536;
    const size_t acc_bstride = (size_t)DD * DD;
    const size_t st_bstride  = (size_t)SS * DD;

    embed_kernel<<<NTOK, 128>>>(toks, emb);
    pack_kernel<<<(DD * 1536 + 255) / 256, 256>>>(Wg, Wu, Wq, Wk, Wv);
    zero_acc_kernel<<<((int)((size_t)VB * DD * DD) + 255) / 256, 256>>>();

    const size_t gu_elems  = (size_t)NTOK * 1536;
    const size_t phi_elems = (size_t)NTOK * 1024;

    for (int step = 0; step < NSTEPS; step++) {
        // n = rms(state)
        rms_kernel<<<NTOK, 128>>>(state, nbuf);
        // GU = n @ [Wg|Wu]
        mma_gemm<EPI_STORE, false><<<dim3(1536 / GBN, NTOK / GBM, 1), 256>>>(
            NTOK, 1536, DD, nbuf, DD, 0, wgu, 1536, 0, big, 1536, 0,
            1.f, 0.f, nullptr, 0, 0);
        act_gu_kernel<<<(unsigned)((gu_elems + 255) / 256), 256>>>();
        // state += gate * (H @ Wd)
        mma_gemm<EPI_GATED, false><<<dim3(DD / GBN, NTOK / GBM, 1), 256>>>(
            NTOK, DD, 2 * DD, big + DD, 1536, 0, Wd, DD, 0, state, DD, 0,
            1.f, 0.f, big, 1536, 0);
        // n2 = rms(state)
        rms_kernel<<<NTOK, 128>>>(state, nbuf);
        // QKV = n2 @ [Wq|Wk|Wv]
        mma_gemm<EPI_STORE, false><<<dim3(1536 / GBN, NTOK / GBM, 1), 256>>>(
            NTOK, 1536, DD, nbuf, DD, 0, wqkv, 1536, 0, big, 1536, 0,
            1.f, 0.f, nullptr, 0, 0);
        act_phi_kernel<<<(unsigned)((phi_elems + 255) / 256), 256>>>();
        // acc = DECAY*acc + inv_s * k^T @ v (batched)
        mma_gemm<EPI_BETA, true><<<dim3(DD / GBN, DD / GBM, VB), 256>>>(
            DD, DD, SS,
            big + DD, 1536, qkv_bstride,
            big + 2 * DD, 1536, qkv_bstride,
            acc, DD, acc_bstride, inv_s, DECAYF, nullptr, 0, 0);
        // accWo = acc @ Wo (batched)
        mma_gemm<EPI_STORE, false><<<dim3(DD / GBN, DD / GBM, VB), 256>>>(
            DD, DD, DD, acc, DD, acc_bstride, Wo, DD, 0,
            accWo, DD, acc_bstride, 1.f, 0.f, nullptr, 0, 0);
        // state += inv_sqrt_d * q @ accWo (batched)
        mma_gemm<EPI_ADD, false><<<dim3(DD / GBN, SS / GBM, VB), 256>>>(
            SS, DD, DD, big, 1536, qkv_bstride, accWo, DD, acc_bstride,
            state, DD, st_bstride, inv_sqrt_d, 0.f, nullptr, 0, 0);
    }

    combine_rms_kernel<<<BATCH * SS, 128>>>();
    mma_gemm<EPI_STORE, false><<<dim3(NVOCAB / GBN, (BATCH * SS) / GBM, 1), 256>>>(
        BATCH * SS, NVOCAB, DD, cmb, DD, 0, Wlm, NVOCAB, 0, out, NVOCAB, 0,
        1.f, 0.f, nullptr, 0, 0);
    (void)in_sizes; (void)n_in; (void)out_size;
}

// round 3
// speedup vs baseline: 2.2193x; 1.3723x over previous
#include <cuda_runtime.h>
#include <cuda_bf16.h>
#include <math.h>
#include <stdint.h>

// ---------------- problem constants ----------------
#define DD     512
#define SS     2048
#define BATCH  8
#define VB     16
#define NTOK   32768
#define NVOCAB 8192
#define NSTEPS 16
#define DECAYF 0.999f
#define EPSF   1e-6f

typedef __nv_bfloat16 bf;
typedef __nv_bfloat162 bf2;

// ---------------- scratch (static device globals; allocation-free) ----------------
__device__ float g_state[(size_t)NTOK * DD];
__device__ float g_gate [(size_t)NTOK * DD];
__device__ float g_accf [(size_t)VB * DD * DD];

__device__ bf g_nh[(size_t)NTOK * DD],  g_nl[(size_t)NTOK * DD];
__device__ bf g_Hh[(size_t)NTOK * 2 * DD], g_Hl[(size_t)NTOK * 2 * DD];
__device__ bf g_qh[(size_t)NTOK * DD],  g_ql[(size_t)NTOK * DD];
__device__ bf g_kh[(size_t)NTOK * DD],  g_kl[(size_t)NTOK * DD];
__device__ bf g_vh[(size_t)NTOK * DD],  g_vl[(size_t)NTOK * DD];
__device__ bf g_acch[(size_t)VB * DD * DD], g_accl[(size_t)VB * DD * DD];
__device__ bf g_awh [(size_t)VB * DD * DD], g_awl [(size_t)VB * DD * DD];
__device__ bf g_cmbh[(size_t)BATCH * SS * DD], g_cmbl[(size_t)BATCH * SS * DD];

__device__ bf g_wguh [DD * 1536], g_wgul [DD * 1536];
__device__ bf g_wqkvh[DD * 1536], g_wqkvl[DD * 1536];
__device__ bf g_wdh  [2 * DD * DD], g_wdl [2 * DD * DD];
__device__ bf g_woh  [DD * DD],     g_wol [DD * DD];
__device__ bf g_wlmh [DD * NVOCAB], g_wlml[DD * NVOCAB];

// ---------------- helpers ----------------
__device__ __forceinline__ void splitstore(bf* __restrict__ Ph, bf* __restrict__ Pl,
                                           size_t off, float x, float y)
{
    bf hx = __float2bfloat16_rn(x), hy = __float2bfloat16_rn(y);
    bf2 h; h.x = hx; h.y = hy;
    bf2 l; l.x = __float2bfloat16_rn(x - __bfloat162float(hx));
           l.y = __float2bfloat16_rn(y - __bfloat162float(hy));
    *reinterpret_cast<bf2*>(Ph + off) = h;
    *reinterpret_cast<bf2*>(Pl + off) = l;
}
__device__ __forceinline__ void split1(float x, bf& h, bf& l)
{
    h = __float2bfloat16_rn(x);
    l = __float2bfloat16_rn(x - __bfloat162float(h));
}
__device__ __forceinline__ float sigf(float x) { return 1.0f / (1.0f + expf(-x)); }
__device__ __forceinline__ float geluf(float x)
{ return 0.5f * x * (1.0f + erff(x * 0.70710678118654752f)); }
__device__ __forceinline__ float phif(float x) { return (x > 0.f) ? x + 1.f : expf(x); }

__device__ __forceinline__ void cp16(void* dst, const void* src)
{
    uint32_t d = (uint32_t)__cvta_generic_to_shared(dst);
    asm volatile("cp.async.cg.shared.global [%0], [%1], 16;" :: "r"(d), "l"(src));
}
__device__ __forceinline__ void cp_commit() { asm volatile("cp.async.commit_group;" ::: "memory"); }
__device__ __forceinline__ void cp_wait1()  { asm volatile("cp.async.wait_group 1;" ::: "memory"); }

__device__ __forceinline__ void ldsm4(uint32_t r[4], const void* p)
{
    uint32_t a = (uint32_t)__cvta_generic_to_shared(p);
    asm volatile("ldmatrix.sync.aligned.m8n8.x4.shared.b16 {%0,%1,%2,%3}, [%4];"
                 : "=r"(r[0]), "=r"(r[1]), "=r"(r[2]), "=r"(r[3]) : "r"(a));
}
__device__ __forceinline__ void ldsm4t(uint32_t r[4], const void* p)
{
    uint32_t a = (uint32_t)__cvta_generic_to_shared(p);
    asm volatile("ldmatrix.sync.aligned.m8n8.x4.trans.shared.b16 {%0,%1,%2,%3}, [%4];"
                 : "=r"(r[0]), "=r"(r[1]), "=r"(r[2]), "=r"(r[3]) : "r"(a));
}
__device__ __forceinline__ void mma16816(float c[4], const uint32_t a[4], const uint32_t b[2])
{
    asm volatile(
        "mma.sync.aligned.m16n8k16.row.col.f32.bf16.bf16.f32 "
        "{%0,%1,%2,%3}, {%4,%5,%6,%7}, {%8,%9}, {%0,%1,%2,%3};"
        : "+f"(c[0]), "+f"(c[1]), "+f"(c[2]), "+f"(c[3])
        : "r"(a[0]), "r"(a[1]), "r"(a[2]), "r"(a[3]), "r"(b[0]), "r"(b[1]));
}

// ---------------- pipelined bf16x3 tensor-core GEMM ----------------
#define GBM 128
#define GBN 128
#define GBK 32
#define ASTR 40     // smem A row stride (elems) for NN layout [m][k]
#define BSTR 136    // smem row stride (elems) for [k][n] / [k][m] layouts
#define STAGES 3

enum { EPI_STORE = 0, EPI_GU = 1, EPI_GATED = 2, EPI_QKV = 3,
       EPI_ACC = 4, EPI_PLANES = 5, EPI_ADD = 6 };

template <int EPI, bool TRANSA>
__global__ void __launch_bounds__(256, 1) gemm(
    int M, int N, int K,
    const bf* __restrict__ Ah, const bf* __restrict__ Al, int lda, size_t sA,
    const bf* __restrict__ Bh, const bf* __restrict__ Bl, int ldb, size_t sB,
    float alpha, float beta,
    float* __restrict__ C, int ldc, size_t sC,
    bf* __restrict__ Ph, bf* __restrict__ Pl, int ldp, size_t sP,
    bf* __restrict__ P2h, bf* __restrict__ P2l,
    bf* __restrict__ P3h, bf* __restrict__ P3l,
    const float* __restrict__ Gate)
{
    const int z = blockIdx.z;
    Ah += (size_t)z * sA;  Al += (size_t)z * sA;
    Bh += (size_t)z * sB;  Bl += (size_t)z * sB;
    if (C)  C  += (size_t)z * sC;
    if (Ph) { Ph += (size_t)z * sP; Pl += (size_t)z * sP; }

    constexpr int A_PL = TRANSA ? (GBK * BSTR) : (GBM * ASTR);
    constexpr int B_PL = GBK * BSTR;
    constexpr int STG  = 2 * A_PL + 2 * B_PL;
    extern __shared__ __align__(16) bf sm[];

    const int tid = threadIdx.x, lane = tid & 31, warp = tid >> 5;
    const int wm = warp & 3, wn = warp >> 2;
    const size_t m_blk = (size_t)blockIdx.y * GBM;
    const size_t n_blk = (size_t)blockIdx.x * GBN;
    const int KT = K / GBK;

    float acc[2][8][4];
#pragma unroll
    for (int mi = 0; mi < 2; mi++)
#pragma unroll
        for (int ni = 0; ni < 8; ni++)
#pragma unroll
            for (int v = 0; v < 4; v++) acc[mi][ni][v] = 0.f;

    auto issue = [&](int kt) {
        if (kt >= KT) { cp_commit(); return; }
        const int st = kt % STAGES;
        const int k0 = kt * GBK;
        bf* dA = sm + st * STG;
        bf* dB = dA + 2 * A_PL;
#pragma unroll
        for (int i = 0; i < 4; i++) {
            int ch = tid + i * 256;
            int pl = ch >> 9;
            const bf* sp = pl ? Al : Ah;
            if (!TRANSA) {
                int r = (ch >> 2) & 127, kc = (ch & 3) * 8;
                cp16(dA + pl * A_PL + r * ASTR + kc,
                     sp + (m_blk + r) * (size_t)lda + k0 + kc);
            } else {
                int r = (ch & 511) >> 4, c = (ch & 15) * 8;
                cp16(dA + pl * A_PL + r * BSTR + c,
                     sp + (size_t)(k0 + r) * lda + m_blk + c);
            }
        }
#pragma unroll
        for (int i = 0; i < 4; i++) {
            int ch = tid + i * 256;
            int pl = ch >> 9, r = (ch & 511) >> 4, c = (ch & 15) * 8;
            const bf* sp = pl ? Bl : Bh;
            cp16(dB + pl * B_PL + r * BSTR + c,
                 sp + (size_t)(k0 + r) * ldb + n_blk + c);
        }
        cp_commit();
    };

    issue(0);
    issue(1);

    for (int kt = 0; kt < KT; kt++) {
        cp_wait1();
        __syncthreads();
        issue(kt + 2);

        const bf* Ahs = sm + (kt % STAGES) * STG;
        const bf* Als = Ahs + A_PL;
        const bf* Bhs = Ahs + 2 * A_PL;
        const bf* Bls = Bhs + B_PL;

#pragma unroll
        for (int ks = 0; ks < 2; ks++) {
            const int kk = ks * 16;
            uint32_t ah[2][4], al[2][4];
            if (!TRANSA) {
                const int ar = lane & 15;
                const int ac = kk + (lane >> 4) * 8;
#pragma unroll
                for (int mi = 0; mi < 2; mi++) {
                    ldsm4(ah[mi], Ahs + (size_t)(wm * 32 + mi * 16 + ar) * ASTR + ac);
                    ldsm4(al[mi], Als + (size_t)(wm * 32 + mi * 16 + ar) * ASTR + ac);
                }
            } else {
                const int q = lane >> 3;
                const int arow = kk + (q >> 1) * 8 + (lane & 7);
#pragma unroll
                for (int mi = 0; mi < 2; mi++) {
                    const int acol = wm * 32 + mi * 16 + (q & 1) * 8;
                    ldsm4t(ah[mi], Ahs + (size_t)arow * BSTR + acol);
                    ldsm4t(al[mi], Als + (size_t)arow * BSTR + acol);
                }
            }
            uint32_t bh[8][2], bl[8][2];
            const int q = lane >> 3;
            const int br = kk + (q & 1) * 8 + (lane & 7);
#pragma unroll
            for (int nt = 0; nt < 4; nt++) {
                const int bc = wn * 64 + nt * 16 + (q >> 1) * 8;
                uint32_t r[4];
                ldsm4t(r, Bhs + (size_t)br * BSTR + bc);
                bh[2 * nt][0] = r[0]; bh[2 * nt][1] = r[1];
                bh[2 * nt + 1][0] = r[2]; bh[2 * nt + 1][1] = r[3];
                ldsm4t(r, Bls + (size_t)br * BSTR + bc);
                bl[2 * nt][0] = r[0]; bl[2 * nt][1] = r[1];
                bl[2 * nt + 1][0] = r[2]; bl[2 * nt + 1][1] = r[3];
            }
#pragma unroll
            for (int mi = 0; mi < 2; mi++)
#pragma unroll
                for (int ni = 0; ni < 8; ni++) {
                    mma16816(acc[mi][ni], ah[mi], bh[ni]);
                    mma16816(acc[mi][ni], ah[mi], bl[ni]);
                    mma16816(acc[mi][ni], al[mi], bh[ni]);
                }
        }
    }

    // ---- epilogue ----
    const int g = lane >> 2, tg = lane & 3;
    const bool isGate = (EPI == EPI_GU) && (n_blk < 512);
    bf* PhSel = Ph; bf* PlSel = Pl;
    bool doPhi = true;
    if (EPI == EPI_QKV) {
        const int reg = (int)(n_blk >> 9);
        if (reg == 1) { PhSel = P2h; PlSel = P2l; }
        else if (reg == 2) { PhSel = P3h; PlSel = P3l; doPhi = false; }
    }

#pragma unroll
    for (int mi = 0; mi < 2; mi++) {
        size_t rr[2];
        rr[0] = m_blk + wm * 32 + mi * 16 + g;
        rr[1] = rr[0] + 8;
#pragma unroll
        for (int ni = 0; ni < 8; ni++) {
            size_t col = n_blk + wn * 64 + ni * 8 + tg * 2;
#pragma unroll
            for (int h = 0; h < 2; h++) {
                size_t row = rr[h];
                float x = alpha * acc[mi][ni][2 * h];
                float y = alpha * acc[mi][ni][2 * h + 1];
                if (EPI == EPI_STORE) {
                    float2 t = make_float2(x, y);
                    *reinterpret_cast<float2*>(C + row * ldc + col) = t;
                } else if (EPI == EPI_ADD) {
                    float2* p = reinterpret_cast<float2*>(C + row * ldc + col);
                    float2 c = *p; c.x += x; c.y += y; *p = c;
                } else if (EPI == EPI_GATED) {
                    float2* p = reinterpret_cast<float2*>(C + row * ldc + col);
                    float2 gg = *reinterpret_cast<const float2*>(Gate + row * 512 + col);
                    float2 c = *p; c.x += gg.x * x; c.y += gg.y * y; *p = c;
                } else if (EPI == EPI_GU) {
                    if (isGate) {
                        float2 t = make_float2(sigf(x), sigf(y));
                        *reinterpret_cast<float2*>(C + row * 512 + col) = t;
                    } else {
                        splitstore(Ph, Pl, row * (size_t)1024 + (col - 512),
                                   geluf(x), geluf(y));
                    }
                } else if (EPI == EPI_QKV) {
                    float a = x, b = y;
                    if (doPhi) { a = phif(a); b = phif(b); }
                    splitstore(PhSel, PlSel, row * (size_t)512 + (col & 511), a, b);
                } else if (EPI == EPI_ACC) {
                    float2* p = reinterpret_cast<float2*>(C + row * ldc + col);
                    float2 c = *p;
                    c.x = beta * c.x + x; c.y = beta * c.y + y;
                    *p = c;
                    splitstore(Ph, Pl, row * (size_t)ldp + col, c.x, c.y);
                } else { // EPI_PLANES
                    splitstore(Ph, Pl, row * (size_t)ldp + col, x, y);
                }
            }
        }
    }
}

// ---------------- elementwise / norm kernels ----------------
__global__ void rms_planes(const float* __restrict__ x,
                           bf* __restrict__ yh, bf* __restrict__ yl)
{
    size_t row = blockIdx.x;
    int t = threadIdx.x;
    float4 v = reinterpret_cast<const float4*>(x + row * DD)[t];
    float ss = v.x * v.x + v.y * v.y + v.z * v.z + v.w * v.w;
#pragma unroll
    for (int o = 16; o > 0; o >>= 1) ss += __shfl_xor_sync(0xffffffffu, ss, o);
    __shared__ float sb[4];
    if ((t & 31) == 0) sb[t >> 5] = ss;
    __syncthreads();
    float tot = sb[0] + sb[1] + sb[2] + sb[3];
    float r = rsqrtf(tot * (1.0f / DD) + EPSF);
    splitstore(yh, yl, row * DD + 4 * t,     v.x * r, v.y * r);
    splitstore(yh, yl, row * DD + 4 * t + 2, v.z * r, v.w * r);
}

__global__ void combine_rms_planes()
{
    size_t row = blockIdx.x;
    int t = threadIdx.x;
    float4 a = reinterpret_cast<const float4*>(g_state + row * DD)[t];
    float4 b = reinterpret_cast<const float4*>(g_state + (row + (size_t)BATCH * SS) * DD)[t];
    float4 v = make_float4(0.5f * (a.x + b.x), 0.5f * (a.y + b.y),
                           0.5f * (a.z + b.z), 0.5f * (a.w + b.w));
    float ss = v.x * v.x + v.y * v.y + v.z * v.z + v.w * v.w;
#pragma unroll
    for (int o = 16; o > 0; o >>= 1) ss += __shfl_xor_sync(0xffffffffu, ss, o);
    __shared__ float sb[4];
    if ((t & 31) == 0) sb[t >> 5] = ss;
    __syncthreads();
    float tot = sb[0] + sb[1] + sb[2] + sb[3];
    float r = rsqrtf(tot * (1.0f / DD) + EPSF);
    splitstore(g_cmbh, g_cmbl, row * DD + 4 * t,     v.x * r, v.y * r);
    splitstore(g_cmbh, g_cmbl, row * DD + 4 * t + 2, v.z * r, v.w * r);
}

__global__ void embed_kernel(const int* __restrict__ toks, const float* __restrict__ emb)
{
    size_t row = blockIdx.x;
    int t = threadIdx.x;
    int s = (int)(row & (SS - 1));
    int vb = (int)(row >> 11);
    int b = vb & 7, v = vb >> 3;
    int tok = toks[b * SS + s];
    const float4* src = reinterpret_cast<const float4*>(
        emb + ((size_t)v * NVOCAB + tok) * DD);
    reinterpret_cast<float4*>(g_state + row * DD)[t] = src[t];
}

__global__ void pack_w(const float* __restrict__ Wg, const float* __restrict__ Wu,
                       const float* __restrict__ Wq, const float* __restrict__ Wk,
                       const float* __restrict__ Wv)
{
    int idx = blockIdx.x * blockDim.x + threadIdx.x;
    if (idx >= DD * 1536) return;
    int r = idx / 1536, c = idx % 1536;
    float a = (c < DD) ? Wg[r * DD + c] : Wu[r * (2 * DD) + (c - DD)];
    split1(a, g_wguh[idx], g_wgul[idx]);
    float q;
    if (c < DD)            q = Wq[r * DD + c];
    else if (c < 2 * DD)   q = Wk[r * DD + (c - DD)];
    else                   q = Wv[r * DD + (c - 2 * DD)];
    split1(q, g_wqkvh[idx], g_wqkvl[idx]);
}

__global__ void convw(const float* __restrict__ s, bf* __restrict__ h,
                      bf* __restrict__ l, int n)
{
    int i = blockIdx.x * blockDim.x + threadIdx.x;
    if (i < n) split1(s[i], h[i], l[i]);
}

__global__ void zero_accf()
{
    size_t i = (size_t)blockIdx.x * blockDim.x + threadIdx.x;
    if (i < (size_t)VB * DD * DD) g_accf[i] = 0.f;
}

// ---------------- host launch ----------------
template <typename T>
static T* sym_addr(const void* sym)
{
    void* p = nullptr;
    cudaGetSymbolAddress(&p, sym);
    return (T*)p;
}

extern "C" void kernel_launch(void* const* d_in, const int* in_sizes, int n_in,
                              void* d_out, int out_size)
{
    const int*   toks = (const int*)d_in[0];
    const float* emb  = (const float*)d_in[1];
    const float* Wg   = (const float*)d_in[2];
    const float* Wu   = (const float*)d_in[3];
    const float* Wd   = (const float*)d_in[4];
    const float* Wq   = (const float*)d_in[5];
    const float* Wk   = (const float*)d_in[6];
    const float* Wv   = (const float*)d_in[7];
    const float* Wo   = (const float*)d_in[8];
    const float* Wlm  = (const float*)d_in[9];
    float* out = (float*)d_out;

    float* state = sym_addr<float>(g_state);
    float* gate  = sym_addr<float>(g_gate);
    float* accf  = sym_addr<float>(g_accf);
    bf* nh = sym_addr<bf>(g_nh);   bf* nl = sym_addr<bf>(g_nl);
    bf* Hh = sym_addr<bf>(g_Hh);   bf* Hl = sym_addr<bf>(g_Hl);
    bf* qh = sym_addr<bf>(g_qh);   bf* ql = sym_addr<bf>(g_ql);
    bf* kh = sym_addr<bf>(g_kh);   bf* kl = sym_addr<bf>(g_kl);
    bf* vh = sym_addr<bf>(g_vh);   bf* vl = sym_addr<bf>(g_vl);
    bf* acch = sym_addr<bf>(g_acch); bf* accl = sym_addr<bf>(g_accl);
    bf* awh = sym_addr<bf>(g_awh);   bf* awl = sym_addr<bf>(g_awl);
    bf* cmbh = sym_addr<bf>(g_cmbh); bf* cmbl = sym_addr<bf>(g_cmbl);
    bf* wguh = sym_addr<bf>(g_wguh); bf* wgul = sym_addr<bf>(g_wgul);
    bf* wqkvh = sym_addr<bf>(g_wqkvh); bf* wqkvl = sym_addr<bf>(g_wqkvl);
    bf* wdh = sym_addr<bf>(g_wdh);   bf* wdl = sym_addr<bf>(g_wdl);
    bf* woh = sym_addr<bf>(g_woh);   bf* wol = sym_addr<bf>(g_wol);
    bf* wlmh = sym_addr<bf>(g_wlmh); bf* wlml = sym_addr<bf>(g_wlml);

    const int SMEM_NN = STAGES * (2 * GBM * ASTR + 2 * GBK * BSTR) * 2;
    const int SMEM_TN = STAGES * (2 * GBK * BSTR + 2 * GBK * BSTR) * 2;

    cudaFuncSetAttribute((const void*)gemm<EPI_GU,     false>, cudaFuncAttributeMaxDynamicSharedMemorySize, SMEM_NN);
    cudaFuncSetAttribute((const void*)gemm<EPI_GATED,  false>, cudaFuncAttributeMaxDynamicSharedMemorySize, SMEM_NN);
    cudaFuncSetAttribute((const void*)gemm<EPI_QKV,    false>, cudaFuncAttributeMaxDynamicSharedMemorySize, SMEM_NN);
    cudaFuncSetAttribute((const void*)gemm<EPI_ACC,    true >, cudaFuncAttributeMaxDynamicSharedMemorySize, SMEM_TN);
    cudaFuncSetAttribute((const void*)gemm<EPI_PLANES, false>, cudaFuncAttributeMaxDynamicSharedMemorySize, SMEM_NN);
    cudaFuncSetAttribute((const void*)gemm<EPI_ADD,    false>, cudaFuncAttributeMaxDynamicSharedMemorySize, SMEM_NN);
    cudaFuncSetAttribute((const void*)gemm<EPI_STORE,  false>, cudaFuncAttributeMaxDynamicSharedMemorySize, SMEM_NN);

    const float inv_s      = 1.0f / (float)SS;
    const float inv_sqrt_d = 1.0f / sqrtf((float)DD);
    const size_t tok_str = (size_t)SS * DD;      // per-batch activation stride
    const size_t acc_str = (size_t)DD * DD;

    embed_kernel<<<NTOK, 128>>>(toks, emb);
    pack_w<<<(DD * 1536 + 255) / 256, 256>>>(Wg, Wu, Wq, Wk, Wv);
    convw<<<(2 * DD * DD + 255) / 256, 256>>>(Wd, wdh, wdl, 2 * DD * DD);
    convw<<<(DD * DD + 255) / 256, 256>>>(Wo, woh, wol, DD * DD);
    convw<<<(DD * NVOCAB + 255) / 256, 256>>>(Wlm, wlmh, wlml, DD * NVOCAB);
    zero_accf<<<(int)(((size_t)VB * DD * DD + 255) / 256), 256>>>();

    for (int step = 0; step < NSTEPS; step++) {
        // n = rms(state) -> planes
        rms_planes<<<NTOK, 128>>>(state, nh, nl);
        // GU = n @ [Wg|Wu]; epilogue: gate=sigmoid (f32), H=gelu (planes)
        gemm<EPI_GU, false><<<dim3(1536 / GBN, NTOK / GBM, 1), 256, SMEM_NN>>>(
            NTOK, 1536, DD, nh, nl, DD, 0, wguh, wgul, 1536, 0,
            1.f, 0.f, gate, DD, 0, Hh, Hl, 1024, 0,
            nullptr, nullptr, nullptr, nullptr, nullptr);
        // state += gate * (H @ Wd)
        gemm<EPI_GATED, false><<<dim3(DD / GBN, NTOK / GBM, 1), 256, SMEM_NN>>>(
            NTOK, DD, 2 * DD, Hh, Hl, 2 * DD, 0, wdh, wdl, DD, 0,
            1.f, 0.f, state, DD, 0, nullptr, nullptr, 0, 0,
            nullptr, nullptr, nullptr, nullptr, gate);
        // n2 = rms(state) -> planes
        rms_planes<<<NTOK, 128>>>(state, nh, nl);
        // QKV = n2 @ [Wq|Wk|Wv]; epilogue: q=phi,k=phi,v raw -> planes
        gemm<EPI_QKV, false><<<dim3(1536 / GBN, NTOK / GBM, 1), 256, SMEM_NN>>>(
            NTOK, 1536, DD, nh, nl, DD, 0, wqkvh, wqkvl, 1536, 0,
            1.f, 0.f, nullptr, 0, 0, qh, ql, DD, 0,
            kh, kl, vh, vl, nullptr);
        // acc = DECAY*acc + inv_s * k^T @ v ; write acc planes
        gemm<EPI_ACC, true><<<dim3(DD / GBN, DD / GBM, VB), 256, SMEM_TN>>>(
            DD, DD, SS, kh, kl, DD, tok_str, vh, vl, DD, tok_str,
            inv_s, DECAYF, accf, DD, acc_str, acch, accl, DD, acc_str,
            nullptr, nullptr, nullptr, nullptr, nullptr);
        // accWo = acc @ Wo -> planes
        gemm<EPI_PLANES, false><<<dim3(DD / GBN, DD / GBM, VB), 256, SMEM_NN>>>(
            DD, DD, DD, acch, accl, DD, acc_str, woh, wol, DD, 0,
            1.f, 0.f, nullptr, 0, 0, awh, awl, DD, acc_str,
            nullptr, nullptr, nullptr, nullptr, nullptr);
        // state += inv_sqrt_d * q @ accWo
        gemm<EPI_ADD, false><<<dim3(DD / GBN, SS / GBM, VB), 256, SMEM_NN>>>(
            SS, DD, DD, qh, ql, DD, tok_str, awh, awl, DD, acc_str,
            inv_sqrt_d, 0.f, state, DD, tok_str, nullptr, nullptr, 0, 0,
            nullptr, nullptr, nullptr, nullptr, nullptr);
    }

    combine_rms_planes<<<BATCH * SS, 128>>>();
    gemm<EPI_STORE, false><<<dim3(NVOCAB / GBN, (BATCH * SS) / GBM, 1), 256, SMEM_NN>>>(
        BATCH * SS, NVOCAB, DD, cmbh, cmbl, DD, 0, wlmh, wlml, NVOCAB, 0,
        1.f, 0.f, out, NVOCAB, 0, nullptr, nullptr, 0, 0,
        nullptr, nullptr, nullptr, nullptr, nullptr);
    (void)in_sizes; (void)n_in; (void)out_size;
}

// round 6
// speedup vs baseline: 2.7722x; 1.2491x over previous
#include <cuda_runtime.h>
#include <cuda_fp16.h>
#include <math.h>
#include <stdint.h>

// ---------------- problem constants ----------------
#define DD     512
#define SS     2048
#define BATCH  8
#define VB     16
#define NTOK   32768
#define NVOCAB 8192
#define NSTEPS 16
#define DECAYF 0.999f
#define EPSF   1e-6f

typedef __half hf;
typedef __half2 hf2;

// ---------------- scratch (static device globals; allocation-free) ----------------
__device__ float g_state[(size_t)NTOK * DD];
__device__ float g_gate [(size_t)NTOK * DD];
__device__ float g_accf [(size_t)VB * DD * DD];

__device__ hf g_nh[(size_t)NTOK * DD],  g_nl[(size_t)NTOK * DD];
__device__ hf g_Hh[(size_t)NTOK * 2 * DD], g_Hl[(size_t)NTOK * 2 * DD];
__device__ hf g_qh[(size_t)NTOK * DD],  g_ql[(size_t)NTOK * DD];
__device__ hf g_kh[(size_t)NTOK * DD],  g_kl[(size_t)NTOK * DD];
__device__ hf g_vh[(size_t)NTOK * DD];                    // hi only (B side)
__device__ hf g_acch[(size_t)VB * DD * DD], g_accl[(size_t)VB * DD * DD];
__device__ hf g_awh [(size_t)VB * DD * DD];               // hi only (B side)
__device__ hf g_cmbh[(size_t)BATCH * SS * DD], g_cmbl[(size_t)BATCH * SS * DD];

// weights: single fp16 plane (B side)
__device__ hf g_wgu [DD * 1536];
__device__ hf g_wqkv[DD * 1536];
__device__ hf g_wd  [2 * DD * DD];
__device__ hf g_wo  [DD * DD];
__device__ hf g_wlm [DD * NVOCAB];

// ---------------- helpers ----------------
__device__ __forceinline__ void split1(float x, hf& h, hf& l)
{
    h = __float2half_rn(x);
    l = __float2half_rn(x - __half2float(h));
}
__device__ __forceinline__ void splitstore(hf* __restrict__ Ph, hf* __restrict__ Pl,
                                           size_t off, float x, float y)
{
    hf hx, lx, hy, ly;
    split1(x, hx, lx); split1(y, hy, ly);
    *reinterpret_cast<hf2*>(Ph + off) = __halves2half2(hx, hy);
    *reinterpret_cast<hf2*>(Pl + off) = __halves2half2(lx, ly);
}
__device__ __forceinline__ float sigf(float x) { return 1.0f / (1.0f + expf(-x)); }
__device__ __forceinline__ float geluf(float x)
{ return 0.5f * x * (1.0f + erff(x * 0.70710678118654752f)); }
__device__ __forceinline__ float phif(float x) { return (x > 0.f) ? x + 1.f : expf(x); }

__device__ __forceinline__ void cp16(void* dst, const void* src)
{
    uint32_t d = (uint32_t)__cvta_generic_to_shared(dst);
    asm volatile("cp.async.cg.shared.global [%0], [%1], 16;" :: "r"(d), "l"(src));
}
__device__ __forceinline__ void cp_commit() { asm volatile("cp.async.commit_group;" ::: "memory"); }
__device__ __forceinline__ void cp_wait1()  { asm volatile("cp.async.wait_group 1;" ::: "memory"); }

__device__ __forceinline__ void ldsm4(uint32_t r[4], const void* p)
{
    uint32_t a = (uint32_t)__cvta_generic_to_shared(p);
    asm volatile("ldmatrix.sync.aligned.m8n8.x4.shared.b16 {%0,%1,%2,%3}, [%4];"
                 : "=r"(r[0]), "=r"(r[1]), "=r"(r[2]), "=r"(r[3]) : "r"(a));
}
__device__ __forceinline__ void ldsm4t(uint32_t r[4], const void* p)
{
    uint32_t a = (uint32_t)__cvta_generic_to_shared(p);
    asm volatile("ldmatrix.sync.aligned.m8n8.x4.trans.shared.b16 {%0,%1,%2,%3}, [%4];"
                 : "=r"(r[0]), "=r"(r[1]), "=r"(r[2]), "=r"(r[3]) : "r"(a));
}
__device__ __forceinline__ void mma16816(float c[4], const uint32_t a[4], const uint32_t b[2])
{
    asm volatile(
        "mma.sync.aligned.m16n8k16.row.col.f32.f16.f16.f32 "
        "{%0,%1,%2,%3}, {%4,%5,%6,%7}, {%8,%9}, {%0,%1,%2,%3};"
        : "+f"(c[0]), "+f"(c[1]), "+f"(c[2]), "+f"(c[3])
        : "r"(a[0]), "r"(a[1]), "r"(a[2]), "r"(a[3]), "r"(b[0]), "r"(b[1]));
}

// ---------------- pipelined fp16 (A=hi+lo, B=hi) tensor-core GEMM ----------------
#define GBM 128
#define GBN 128
#define GBK 32
#define ASTR 40     // smem A row stride (elems) for NN layout [m][k]
#define BSTR 136    // smem row stride (elems) for [k][n] / [k][m] layouts
#define STAGES 3

enum { EPI_STORE = 0, EPI_GU = 1, EPI_GATED = 2, EPI_QKV = 3,
       EPI_ACC = 4, EPI_PLANES = 5, EPI_ADD = 6 };

template <int EPI, bool TRANSA>
__global__ void __launch_bounds__(256, 1) gemm(
    int M, int N, int K,
    const hf* __restrict__ Ah, const hf* __restrict__ Al, int lda, size_t sA,
    const hf* __restrict__ Bh, int ldb, size_t sB,
    float alpha, float beta,
    float* __restrict__ C, int ldc, size_t sC,
    hf* __restrict__ Ph, hf* __restrict__ Pl, int ldp, size_t sP,
    hf* __restrict__ P2h, hf* __restrict__ P2l, hf* __restrict__ P3h,
    const float* __restrict__ Gate)
{
    const int z = blockIdx.z;
    Ah += (size_t)z * sA;  Al += (size_t)z * sA;
    Bh += (size_t)z * sB;
    if (C)  C  += (size_t)z * sC;
    if (Ph) { Ph += (size_t)z * sP; if (Pl) Pl += (size_t)z * sP; }

    constexpr int A_PL = TRANSA ? (GBK * BSTR) : (GBM * ASTR);
    constexpr int B_PL = GBK * BSTR;
    constexpr int STG  = 2 * A_PL + B_PL;
    extern __shared__ __align__(16) hf sm[];

    const int tid = threadIdx.x, lane = tid & 31, warp = tid >> 5;
    const int wm = warp & 3, wn = warp >> 2;
    const size_t m_blk = (size_t)blockIdx.y * GBM;
    const size_t n_blk = (size_t)blockIdx.x * GBN;
    const int KT = K / GBK;

    float acc[2][8][4];
#pragma unroll
    for (int mi = 0; mi < 2; mi++)
#pragma unroll
        for (int ni = 0; ni < 8; ni++)
#pragma unroll
            for (int v = 0; v < 4; v++) acc[mi][ni][v] = 0.f;

    auto issue = [&](int kt) {
        if (kt >= KT) { cp_commit(); return; }
        const int st = kt % STAGES;
        const int k0 = kt * GBK;
        hf* dA = sm + st * STG;
        hf* dB = dA + 2 * A_PL;
        // A: 2 planes
#pragma unroll
        for (int i = 0; i < 4; i++) {
            int ch = tid + i * 256;
            int pl = ch >> 9;
            const hf* sp = pl ? Al : Ah;
            if (!TRANSA) {
                int r = (ch >> 2) & 127, kc = (ch & 3) * 8;
                cp16(dA + pl * A_PL + r * ASTR + kc,
                     sp + (m_blk + r) * (size_t)lda + k0 + kc);
            } else {
                int r = (ch & 511) >> 4, c = (ch & 15) * 8;
                cp16(dA + pl * A_PL + r * BSTR + c,
                     sp + (size_t)(k0 + r) * lda + m_blk + c);
            }
        }
        // B: 1 plane
#pragma unroll
        for (int i = 0; i < 2; i++) {
            int ch = tid + i * 256;
            int r = ch >> 4, c = (ch & 15) * 8;
            cp16(dB + r * BSTR + c,
                 Bh + (size_t)(k0 + r) * ldb + n_blk + c);
        }
        cp_commit();
    };

    issue(0);
    issue(1);

    for (int kt = 0; kt < KT; kt++) {
        cp_wait1();
        __syncthreads();
        issue(kt + 2);

        const hf* Ahs = sm + (kt % STAGES) * STG;
        const hf* Als = Ahs + A_PL;
        const hf* Bhs = Ahs + 2 * A_PL;

#pragma unroll
        for (int ks = 0; ks < 2; ks++) {
            const int kk = ks * 16;
            uint32_t ah[2][4], al[2][4];
            if (!TRANSA) {
                const int ar = lane & 15;
                const int ac = kk + (lane >> 4) * 8;
#pragma unroll
                for (int mi = 0; mi < 2; mi++) {
                    ldsm4(ah[mi], Ahs + (size_t)(wm * 32 + mi * 16 + ar) * ASTR + ac);
                    ldsm4(al[mi], Als + (size_t)(wm * 32 + mi * 16 + ar) * ASTR + ac);
                }
            } else {
                const int q = lane >> 3;
                const int arow = kk + (q >> 1) * 8 + (lane & 7);
#pragma unroll
                for (int mi = 0; mi < 2; mi++) {
                    const int acol = wm * 32 + mi * 16 + (q & 1) * 8;
                    ldsm4t(ah[mi], Ahs + (size_t)arow * BSTR + acol);
                    ldsm4t(al[mi], Als + (size_t)arow * BSTR + acol);
                }
            }
            uint32_t bh[8][2];
            const int q = lane >> 3;
            const int br = kk + (q & 1) * 8 + (lane & 7);
#pragma unroll
            for (int nt = 0; nt < 4; nt++) {
                const int bc = wn * 64 + nt * 16 + (q >> 1) * 8;
                uint32_t r[4];
                ldsm4t(r, Bhs + (size_t)br * BSTR + bc);
                bh[2 * nt][0] = r[0]; bh[2 * nt][1] = r[1];
                bh[2 * nt + 1][0] = r[2]; bh[2 * nt + 1][1] = r[3];
            }
#pragma unroll
            for (int mi = 0; mi < 2; mi++)
#pragma unroll
                for (int ni = 0; ni < 8; ni++) {
                    mma16816(acc[mi][ni], ah[mi], bh[ni]);
                    mma16816(acc[mi][ni], al[mi], bh[ni]);
                }
        }
    }

    // ---- epilogue ----
    const int g = lane >> 2, tg = lane & 3;
#pragma unroll
    for (int mi = 0; mi < 2; mi++) {
        size_t rr[2];
        rr[0] = m_blk + wm * 32 + mi * 16 + g;
        rr[1] = rr[0] + 8;
#pragma unroll
        for (int ni = 0; ni < 8; ni++) {
            size_t col = n_blk + wn * 64 + ni * 8 + tg * 2;
#pragma unroll
            for (int h = 0; h < 2; h++) {
                size_t row = rr[h];
                float x = alpha * acc[mi][ni][2 * h];
                float y = alpha * acc[mi][ni][2 * h + 1];
                if (EPI == EPI_STORE) {
                    *reinterpret_cast<float2*>(C + row * ldc + col) = make_float2(x, y);
                } else if (EPI == EPI_ADD) {
                    float2* p = reinterpret_cast<float2*>(C + row * ldc + col);
                    float2 c = *p; c.x += x; c.y += y; *p = c;
                } else if (EPI == EPI_GATED) {
                    float2* p = reinterpret_cast<float2*>(C + row * ldc + col);
                    float2 gg = *reinterpret_cast<const float2*>(Gate + row * 512 + col);
                    float2 c = *p; c.x += gg.x * x; c.y += gg.y * y; *p = c;
                } else if (EPI == EPI_GU) {
                    if (col < 512)
                        *reinterpret_cast<float2*>(C + row * 512 + col) =
                            make_float2(sigf(x), sigf(y));
                    else
                        splitstore(Ph, Pl, row * (size_t)1024 + (col - 512),
                                   geluf(x), geluf(y));
                } else if (EPI == EPI_QKV) {
                    const int reg = (int)(col >> 9);
                    if (reg == 0)
                        splitstore(Ph, Pl, row * (size_t)512 + (col & 511),
                                   phif(x), phif(y));
                    else if (reg == 1)
                        splitstore(P2h, P2l, row * (size_t)512 + (col & 511),
                                   phif(x), phif(y));
                    else
                        *reinterpret_cast<hf2*>(P3h + row * (size_t)512 + (col & 511)) =
                            __halves2half2(__float2half_rn(x), __float2half_rn(y));
                } else if (EPI == EPI_ACC) {
                    float2* p = reinterpret_cast<float2*>(C + row * ldc + col);
                    float2 c = *p;
                    c.x = beta * c.x + x; c.y = beta * c.y + y;
                    *p = c;
                    splitstore(Ph, Pl, row * (size_t)ldp + col, c.x, c.y);
                } else { // EPI_PLANES: hi-only store
                    *reinterpret_cast<hf2*>(Ph + row * (size_t)ldp + col) =
                        __halves2half2(__float2half_rn(x), __float2half_rn(y));
                }
            }
        }
    }
}

// ---------------- elementwise / norm kernels ----------------
__global__ void rms_planes(const float* __restrict__ x,
                           hf* __restrict__ yh, hf* __restrict__ yl)
{
    size_t row = blockIdx.x;
    int t = threadIdx.x;
    float4 v = reinterpret_cast<const float4*>(x + row * DD)[t];
    float ss = v.x * v.x + v.y * v.y + v.z * v.z + v.w * v.w;
#pragma unroll
    for (int o = 16; o > 0; o >>= 1) ss += __shfl_xor_sync(0xffffffffu, ss, o);
    __shared__ float sb[4];
    if ((t & 31) == 0) sb[t >> 5] = ss;
    __syncthreads();
    float tot = sb[0] + sb[1] + sb[2] + sb[3];
    float r = rsqrtf(tot * (1.0f / DD) + EPSF);
    splitstore(yh, yl, row * DD + 4 * t,     v.x * r, v.y * r);
    splitstore(yh, yl, row * DD + 4 * t + 2, v.z * r, v.w * r);
}

__global__ void combine_rms_planes()
{
    size_t row = blockIdx.x;
    int t = threadIdx.x;
    float4 a = reinterpret_cast<const float4*>(g_state + row * DD)[t];
    float4 b = reinterpret_cast<const float4*>(g_state + (row + (size_t)BATCH * SS) * DD)[t];
    float4 v = make_float4(0.5f * (a.x + b.x), 0.5f * (a.y + b.y),
                           0.5f * (a.z + b.z), 0.5f * (a.w + b.w));
    float ss = v.x * v.x + v.y * v.y + v.z * v.z + v.w * v.w;
#pragma unroll
    for (int o = 16; o > 0; o >>= 1) ss += __shfl_xor_sync(0xffffffffu, ss, o);
    __shared__ float sb[4];
    if ((t & 31) == 0) sb[t >> 5] = ss;
    __syncthreads();
    float tot = sb[0] + sb[1] + sb[2] + sb[3];
    float r = rsqrtf(tot * (1.0f / DD) + EPSF);
    splitstore(g_cmbh, g_cmbl, row * DD + 4 * t,     v.x * r, v.y * r);
    splitstore(g_cmbh, g_cmbl, row * DD + 4 * t + 2, v.z * r, v.w * r);
}

__global__ void embed_kernel(const int* __restrict__ toks, const float* __restrict__ emb)
{
    size_t row = blockIdx.x;
    int t = threadIdx.x;
    int s = (int)(row & (SS - 1));
    int vb = (int)(row >> 11);
    int b = vb & 7, v = vb >> 3;
    int tok = toks[b * SS + s];
    const float4* src = reinterpret_cast<const float4*>(
        emb + ((size_t)v * NVOCAB + tok) * DD);
    reinterpret_cast<float4*>(g_state + row * DD)[t] = src[t];
}

// pack Wgu = [Wg|Wu], Wqkv = [Wq|Wk|Wv] (row-major 512 x 1536, fp16)
__global__ void pack_w(const float* __restrict__ Wg, const float* __restrict__ Wu,
                       const float* __restrict__ Wq, const float* __restrict__ Wk,
                       const float* __restrict__ Wv)
{
    int idx = blockIdx.x * blockDim.x + threadIdx.x;
    if (idx >= DD * 1536) return;
    int r = idx / 1536, c = idx % 1536;
    float a = (c < DD) ? Wg[r * DD + c] : Wu[r * (2 * DD) + (c - DD)];
    g_wgu[idx] = __float2half_rn(a);
    float q;
    if (c < DD)            q = Wq[r * DD + c];
    else if (c < 2 * DD)   q = Wk[r * DD + (c - DD)];
    else                   q = Wv[r * DD + (c - 2 * DD)];
    g_wqkv[idx] = __float2half_rn(q);
}

__global__ void convw(const float* __restrict__ s, hf* __restrict__ h, int n)
{
    int i = blockIdx.x * blockDim.x + threadIdx.x;
    if (i < n) h[i] = __float2half_rn(s[i]);
}

__global__ void zero_accf()
{
    size_t i = (size_t)blockIdx.x * blockDim.x + threadIdx.x;
    if (i < (size_t)VB * DD * DD) g_accf[i] = 0.f;
}

// ---------------- host launch ----------------
template <typename T>
static T* sym_addr(const void* sym)
{
    void* p = nullptr;
    cudaGetSymbolAddress(&p, sym);
    return (T*)p;
}

extern "C" void kernel_launch(void* const* d_in, const int* in_sizes, int n_in,
                              void* d_out, int out_size)
{
    const int*   toks = (const int*)d_in[0];
    const float* emb  = (const float*)d_in[1];
    const float* Wg   = (const float*)d_in[2];
    const float* Wu   = (const float*)d_in[3];
    const float* Wd   = (const float*)d_in[4];
    const float* Wq   = (const float*)d_in[5];
    const float* Wk   = (const float*)d_in[6];
    const float* Wv   = (const float*)d_in[7];
    const float* Wo   = (const float*)d_in[8];
    const float* Wlm  = (const float*)d_in[9];
    float* out = (float*)d_out;

    float* state = sym_addr<float>(g_state);
    float* gate  = sym_addr<float>(g_gate);
    float* accf  = sym_addr<float>(g_accf);
    hf* nh = sym_addr<hf>(g_nh);   hf* nl = sym_addr<hf>(g_nl);
    hf* Hh = sym_addr<hf>(g_Hh);   hf* Hl = sym_addr<hf>(g_Hl);
    hf* qh = sym_addr<hf>(g_qh);   hf* ql = sym_addr<hf>(g_ql);
    hf* kh = sym_addr<hf>(g_kh);   hf* kl = sym_addr<hf>(g_kl);
    hf* vh = sym_addr<hf>(g_vh);
    hf* acch = sym_addr<hf>(g_acch); hf* accl = sym_addr<hf>(g_accl);
    hf* awh = sym_addr<hf>(g_awh);
    hf* cmbh = sym_addr<hf>(g_cmbh); hf* cmbl = sym_addr<hf>(g_cmbl);
    hf* wgu = sym_addr<hf>(g_wgu);   hf* wqkv = sym_addr<hf>(g_wqkv);
    hf* wd = sym_addr<hf>(g_wd);     hf* wo = sym_addr<hf>(g_wo);
    hf* wlm = sym_addr<hf>(g_wlm);

    const int SMEM_NN = STAGES * (2 * GBM * ASTR + GBK * BSTR) * 2;
    const int SMEM_TN = STAGES * (3 * GBK * BSTR) * 2;

    cudaFuncSetAttribute((const void*)gemm<EPI_GU,     false>, cudaFuncAttributeMaxDynamicSharedMemorySize, SMEM_NN);
    cudaFuncSetAttribute((const void*)gemm<EPI_GATED,  false>, cudaFuncAttributeMaxDynamicSharedMemorySize, SMEM_NN);
    cudaFuncSetAttribute((const void*)gemm<EPI_QKV,    false>, cudaFuncAttributeMaxDynamicSharedMemorySize, SMEM_NN);
    cudaFuncSetAttribute((const void*)gemm<EPI_ACC,    true >, cudaFuncAttributeMaxDynamicSharedMemorySize, SMEM_TN);
    cudaFuncSetAttribute((const void*)gemm<EPI_PLANES, false>, cudaFuncAttributeMaxDynamicSharedMemorySize, SMEM_NN);
    cudaFuncSetAttribute((const void*)gemm<EPI_ADD,    false>, cudaFuncAttributeMaxDynamicSharedMemorySize, SMEM_NN);
    cudaFuncSetAttribute((const void*)gemm<EPI_STORE,  false>, cudaFuncAttributeMaxDynamicSharedMemorySize, SMEM_NN);

    const float inv_s      = 1.0f / (float)SS;
    const float inv_sqrt_d = 1.0f / sqrtf((float)DD);
    const size_t tok_str = (size_t)SS * DD;
    const size_t acc_str = (size_t)DD * DD;

    embed_kernel<<<NTOK, 128>>>(toks, emb);
    pack_w<<<(DD * 1536 + 255) / 256, 256>>>(Wg, Wu, Wq, Wk, Wv);
    convw<<<(2 * DD * DD + 255) / 256, 256>>>(Wd, wd, 2 * DD * DD);
    convw<<<(DD * DD + 255) / 256, 256>>>(Wo, wo, DD * DD);
    convw<<<(DD * NVOCAB + 255) / 256, 256>>>(Wlm, wlm, DD * NVOCAB);
    zero_accf<<<(int)(((size_t)VB * DD * DD + 255) / 256), 256>>>();

    for (int step = 0; step < NSTEPS; step++) {
        rms_planes<<<NTOK, 128>>>(state, nh, nl);
        // GU = n @ [Wg|Wu]: gate=sigmoid f32, H=gelu planes
        gemm<EPI_GU, false><<<dim3(1536 / GBN, NTOK / GBM, 1), 256, SMEM_NN>>>(
            NTOK, 1536, DD, nh, nl, DD, 0, wgu, 1536, 0,
            1.f, 0.f, gate, DD, 0, Hh, Hl, 1024, 0,
            nullptr, nullptr, nullptr, nullptr);
        // state += gate * (H @ Wd)
        gemm<EPI_GATED, false><<<dim3(DD / GBN, NTOK / GBM, 1), 256, SMEM_NN>>>(
            NTOK, DD, 2 * DD, Hh, Hl, 2 * DD, 0, wd, DD, 0,
            1.f, 0.f, state, DD, 0, nullptr, nullptr, 0, 0,
            nullptr, nullptr, nullptr, gate);
        rms_planes<<<NTOK, 128>>>(state, nh, nl);
        // QKV = n2 @ [Wq|Wk|Wv]: phi on q,k; v hi only
        gemm<EPI_QKV, false><<<dim3(1536 / GBN, NTOK / GBM, 1), 256, SMEM_NN>>>(
            NTOK, 1536, DD, nh, nl, DD, 0, wqkv, 1536, 0,
            1.f, 0.f, nullptr, 0, 0, qh, ql, DD, 0,
            kh, kl, vh, nullptr);
        // acc = DECAY*acc + inv_s * k^T @ v (batched); write acc planes
        gemm<EPI_ACC, true><<<dim3(DD / GBN, DD / GBM, VB), 256, SMEM_TN>>>(
            DD, DD, SS, kh, kl, DD, tok_str, vh, DD, tok_str,
            inv_s, DECAYF, accf, DD, acc_str, acch, accl, DD, acc_str,
            nullptr, nullptr, nullptr, nullptr);
        // accWo = acc @ Wo -> hi-only plane (batched)
        gemm<EPI_PLANES, false><<<dim3(DD / GBN, DD / GBM, VB), 256, SMEM_NN>>>(
            DD, DD, DD, acch, accl, DD, acc_str, wo, DD, 0,
            1.f, 0.f, nullptr, 0, 0, awh, nullptr, DD, acc_str,
            nullptr, nullptr, nullptr, nullptr);
        // state += inv_sqrt_d * q @ accWo (batched)
        gemm<EPI_ADD, false><<<dim3(DD / GBN, SS / GBM, VB), 256, SMEM_NN>>>(
            SS, DD, DD, qh, ql, DD, tok_str, awh, DD, acc_str,
            inv_sqrt_d, 0.f, state, DD, tok_str, nullptr, nullptr, 0, 0,
            nullptr, nullptr, nullptr, nullptr);
    }

    combine_rms_planes<<<BATCH * SS, 128>>>();
    gemm<EPI_STORE, false><<<dim3(NVOCAB / GBN, (BATCH * SS) / GBM, 1), 256, SMEM_NN>>>(
        BATCH * SS, NVOCAB, DD, cmbh, cmbl, DD, 0, wlm, NVOCAB, 0,
        1.f, 0.f, out, NVOCAB, 0, nullptr, nullptr, 0, 0,
        nullptr, nullptr, nullptr, nullptr);
    (void)in_sizes; (void)n_in; (void)out_size;
}

// round 7
// speedup vs baseline: 3.9803x; 1.4358x over previous
#include <cuda_runtime.h>
#include <cuda_fp16.h>
#include <math.h>
#include <stdint.h>

// ---------------- problem constants ----------------
#define DD     512
#define SS     2048
#define BATCH  8
#define VB     16
#define NTOK   32768
#define NVOCAB 8192
#define NSTEPS 16
#define DECAYF 0.999f
#define EPSF   1e-6f

typedef __half hf;
typedef __half2 hf2;

// ---------------- scratch (static device globals; allocation-free) ----------------
__device__ float g_state[(size_t)NTOK * DD];
__device__ float g_gate [(size_t)NTOK * DD];
__device__ float g_accf [(size_t)VB * DD * DD];

__device__ hf g_nh[(size_t)NTOK * DD];                    // single plane (A of GU/QKV)
__device__ hf g_Hh[(size_t)NTOK * 2 * DD], g_Hl[(size_t)NTOK * 2 * DD];
__device__ hf g_qh[(size_t)NTOK * DD],  g_ql[(size_t)NTOK * DD];
__device__ hf g_kh[(size_t)NTOK * DD],  g_kl[(size_t)NTOK * DD];
__device__ hf g_vh[(size_t)NTOK * DD];                    // hi only (B side)
__device__ hf g_acch[(size_t)VB * DD * DD], g_accl[(size_t)VB * DD * DD];
__device__ hf g_awh [(size_t)VB * DD * DD];               // hi only (B side)
__device__ hf g_cmbh[(size_t)BATCH * SS * DD];            // single plane (A of LM)

// weights: single fp16 plane (B side)
__device__ hf g_wgu [DD * 1536];
__device__ hf g_wqkv[DD * 1536];
__device__ hf g_wd  [2 * DD * DD];
__device__ hf g_wo  [DD * DD];
__device__ hf g_wlm [DD * NVOCAB];

// ---------------- helpers ----------------
__device__ __forceinline__ void split1(float x, hf& h, hf& l)
{
    h = __float2half_rn(x);
    l = __float2half_rn(x - __half2float(h));
}
__device__ __forceinline__ void splitstore(hf* __restrict__ Ph, hf* __restrict__ Pl,
                                           size_t off, float x, float y)
{
    hf hx, lx, hy, ly;
    split1(x, hx, lx); split1(y, hy, ly);
    *reinterpret_cast<hf2*>(Ph + off) = __halves2half2(hx, hy);
    *reinterpret_cast<hf2*>(Pl + off) = __halves2half2(lx, ly);
}
__device__ __forceinline__ float sigf(float x) { return 1.0f / (1.0f + expf(-x)); }
__device__ __forceinline__ float geluf(float x)
{ return 0.5f * x * (1.0f + erff(x * 0.70710678118654752f)); }
__device__ __forceinline__ float phif(float x) { return (x > 0.f) ? x + 1.f : expf(x); }

__device__ __forceinline__ void cp16(void* dst, const void* src)
{
    uint32_t d = (uint32_t)__cvta_generic_to_shared(dst);
    asm volatile("cp.async.cg.shared.global [%0], [%1], 16;" :: "r"(d), "l"(src));
}
__device__ __forceinline__ void cp_commit() { asm volatile("cp.async.commit_group;" ::: "memory"); }
__device__ __forceinline__ void cp_wait1()  { asm volatile("cp.async.wait_group 1;" ::: "memory"); }

__device__ __forceinline__ void ldsm4(uint32_t r[4], const void* p)
{
    uint32_t a = (uint32_t)__cvta_generic_to_shared(p);
    asm volatile("ldmatrix.sync.aligned.m8n8.x4.shared.b16 {%0,%1,%2,%3}, [%4];"
                 : "=r"(r[0]), "=r"(r[1]), "=r"(r[2]), "=r"(r[3]) : "r"(a));
}
__device__ __forceinline__ void ldsm4t(uint32_t r[4], const void* p)
{
    uint32_t a = (uint32_t)__cvta_generic_to_shared(p);
    asm volatile("ldmatrix.sync.aligned.m8n8.x4.trans.shared.b16 {%0,%1,%2,%3}, [%4];"
                 : "=r"(r[0]), "=r"(r[1]), "=r"(r[2]), "=r"(r[3]) : "r"(a));
}
__device__ __forceinline__ void mma16816(float c[4], const uint32_t a[4], const uint32_t b[2])
{
    asm volatile(
        "mma.sync.aligned.m16n8k16.row.col.f32.f16.f16.f32 "
        "{%0,%1,%2,%3}, {%4,%5,%6,%7}, {%8,%9}, {%0,%1,%2,%3};"
        : "+f"(c[0]), "+f"(c[1]), "+f"(c[2]), "+f"(c[3])
        : "r"(a[0]), "r"(a[1]), "r"(a[2]), "r"(a[3]), "r"(b[0]), "r"(b[1]));
}

// ---------------- pipelined fp16 tensor-core GEMM ----------------
// ALO=true : A = hi+lo planes (2 mma per product)
// ALO=false: A = hi plane only (1 mma per product)
#define GBM 128
#define GBN 128
#define GBK 32
#define ASTR 40     // smem A row stride (elems) for NN layout [m][k]
#define BSTR 136    // smem row stride (elems) for [k][n] / [k][m] layouts
#define STAGES 3

enum { EPI_STORE = 0, EPI_GU = 1, EPI_GATED = 2, EPI_QKV = 3,
       EPI_ACC = 4, EPI_PLANES = 5, EPI_ADD = 6 };

template <int EPI, bool TRANSA, bool ALO>
__global__ void __launch_bounds__(256, ALO ? 1 : 2) gemm(
    int M, int N, int K,
    const hf* __restrict__ Ah, const hf* __restrict__ Al, int lda, size_t sA,
    const hf* __restrict__ Bh, int ldb, size_t sB,
    float alpha, float beta,
    float* __restrict__ C, int ldc, size_t sC,
    hf* __restrict__ Ph, hf* __restrict__ Pl, int ldp, size_t sP,
    hf* __restrict__ P2h, hf* __restrict__ P2l, hf* __restrict__ P3h,
    const float* __restrict__ Gate)
{
    const int z = blockIdx.z;
    Ah += (size_t)z * sA;
    if (ALO) Al += (size_t)z * sA;
    Bh += (size_t)z * sB;
    if (C)  C  += (size_t)z * sC;
    if (Ph) { Ph += (size_t)z * sP; if (Pl) Pl += (size_t)z * sP; }

    constexpr int NPL  = ALO ? 2 : 1;
    constexpr int A_PL = TRANSA ? (GBK * BSTR) : (GBM * ASTR);
    constexpr int B_PL = GBK * BSTR;
    constexpr int STG  = NPL * A_PL + B_PL;
    extern __shared__ __align__(16) hf sm[];

    const int tid = threadIdx.x, lane = tid & 31, warp = tid >> 5;
    const int wm = warp & 3, wn = warp >> 2;
    const size_t m_blk = (size_t)blockIdx.y * GBM;
    const size_t n_blk = (size_t)blockIdx.x * GBN;
    const int KT = K / GBK;

    float acc[2][8][4];
#pragma unroll
    for (int mi = 0; mi < 2; mi++)
#pragma unroll
        for (int ni = 0; ni < 8; ni++)
#pragma unroll
            for (int v = 0; v < 4; v++) acc[mi][ni][v] = 0.f;

    auto issue = [&](int kt) {
        if (kt >= KT) { cp_commit(); return; }
        const int st = kt % STAGES;
        const int k0 = kt * GBK;
        hf* dA = sm + st * STG;
        hf* dB = dA + NPL * A_PL;
        // A: NPL planes, 512 chunks each
#pragma unroll
        for (int i = 0; i < 2 * NPL; i++) {
            int ch = tid + i * 256;
            int pl = ALO ? (ch >> 9) : 0;
            const hf* sp = (ALO && pl) ? Al : Ah;
            if (!TRANSA) {
                int r = (ch >> 2) & 127, kc = (ch & 3) * 8;
                cp16(dA + pl * A_PL + r * ASTR + kc,
                     sp + (m_blk + r) * (size_t)lda + k0 + kc);
            } else {
                int r = (ch & 511) >> 4, c = (ch & 15) * 8;
                cp16(dA + pl * A_PL + r * BSTR + c,
                     sp + (size_t)(k0 + r) * lda + m_blk + c);
            }
        }
        // B: 1 plane
#pragma unroll
        for (int i = 0; i < 2; i++) {
            int ch = tid + i * 256;
            int r = ch >> 4, c = (ch & 15) * 8;
            cp16(dB + r * BSTR + c,
                 Bh + (size_t)(k0 + r) * ldb + n_blk + c);
        }
        cp_commit();
    };

    issue(0);
    issue(1);

    for (int kt = 0; kt < KT; kt++) {
        cp_wait1();
        __syncthreads();
        issue(kt + 2);

        const hf* Ahs = sm + (kt % STAGES) * STG;
        const hf* Als = Ahs + A_PL;
        const hf* Bhs = Ahs + NPL * A_PL;

#pragma unroll
        for (int ks = 0; ks < 2; ks++) {
            const int kk = ks * 16;
            uint32_t ah[2][4], al[2][4];
            if (!TRANSA) {
                const int ar = lane & 15;
                const int ac = kk + (lane >> 4) * 8;
#pragma unroll
                for (int mi = 0; mi < 2; mi++) {
                    ldsm4(ah[mi], Ahs + (size_t)(wm * 32 + mi * 16 + ar) * ASTR + ac);
                    if (ALO)
                        ldsm4(al[mi], Als + (size_t)(wm * 32 + mi * 16 + ar) * ASTR + ac);
                }
            } else {
                const int q = lane >> 3;
                const int arow = kk + (q >> 1) * 8 + (lane & 7);
#pragma unroll
                for (int mi = 0; mi < 2; mi++) {
                    const int acol = wm * 32 + mi * 16 + (q & 1) * 8;
                    ldsm4t(ah[mi], Ahs + (size_t)arow * BSTR + acol);
                    if (ALO)
                        ldsm4t(al[mi], Als + (size_t)arow * BSTR + acol);
                }
            }
            uint32_t bh[8][2];
            const int q = lane >> 3;
            const int br = kk + (q & 1) * 8 + (lane & 7);
#pragma unroll
            for (int nt = 0; nt < 4; nt++) {
                const int bc = wn * 64 + nt * 16 + (q >> 1) * 8;
                uint32_t r[4];
                ldsm4t(r, Bhs + (size_t)br * BSTR + bc);
                bh[2 * nt][0] = r[0]; bh[2 * nt][1] = r[1];
                bh[2 * nt + 1][0] = r[2]; bh[2 * nt + 1][1] = r[3];
            }
#pragma unroll
            for (int mi = 0; mi < 2; mi++)
#pragma unroll
                for (int ni = 0; ni < 8; ni++) {
                    mma16816(acc[mi][ni], ah[mi], bh[ni]);
                    if (ALO) mma16816(acc[mi][ni], al[mi], bh[ni]);
                }
        }
    }

    // ---- epilogue ----
    const int g = lane >> 2, tg = lane & 3;
#pragma unroll
    for (int mi = 0; mi < 2; mi++) {
        size_t rr[2];
        rr[0] = m_blk + wm * 32 + mi * 16 + g;
        rr[1] = rr[0] + 8;
#pragma unroll
        for (int ni = 0; ni < 8; ni++) {
            size_t col = n_blk + wn * 64 + ni * 8 + tg * 2;
#pragma unroll
            for (int h = 0; h < 2; h++) {
                size_t row = rr[h];
                float x = alpha * acc[mi][ni][2 * h];
                float y = alpha * acc[mi][ni][2 * h + 1];
                if (EPI == EPI_STORE) {
                    *reinterpret_cast<float2*>(C + row * ldc + col) = make_float2(x, y);
                } else if (EPI == EPI_ADD) {
                    float2* p = reinterpret_cast<float2*>(C + row * ldc + col);
                    float2 c = *p; c.x += x; c.y += y; *p = c;
                } else if (EPI == EPI_GATED) {
                    float2* p = reinterpret_cast<float2*>(C + row * ldc + col);
                    float2 gg = *reinterpret_cast<const float2*>(Gate + row * 512 + col);
                    float2 c = *p; c.x += gg.x * x; c.y += gg.y * y; *p = c;
                } else if (EPI == EPI_GU) {
                    if (col < 512)
                        *reinterpret_cast<float2*>(C + row * 512 + col) =
                            make_float2(sigf(x), sigf(y));
                    else
                        splitstore(Ph, Pl, row * (size_t)1024 + (col - 512),
                                   geluf(x), geluf(y));
                } else if (EPI == EPI_QKV) {
                    const int reg = (int)(col >> 9);
                    if (reg == 0)
                        splitstore(Ph, Pl, row * (size_t)512 + (col & 511),
                                   phif(x), phif(y));
                    else if (reg == 1)
                        splitstore(P2h, P2l, row * (size_t)512 + (col & 511),
                                   phif(x), phif(y));
                    else
                        *reinterpret_cast<hf2*>(P3h + row * (size_t)512 + (col & 511)) =
                            __floats2half2_rn(x, y);
                } else if (EPI == EPI_ACC) {
                    float2* p = reinterpret_cast<float2*>(C + row * ldc + col);
                    float2 c = *p;
                    c.x = beta * c.x + x; c.y = beta * c.y + y;
                    *p = c;
                    splitstore(Ph, Pl, row * (size_t)ldp + col, c.x, c.y);
                } else { // EPI_PLANES: hi-only store
                    *reinterpret_cast<hf2*>(Ph + row * (size_t)ldp + col) =
                        __floats2half2_rn(x, y);
                }
            }
        }
    }
}

// ---------------- elementwise / norm kernels ----------------
__global__ void rms_single(const float* __restrict__ x, hf* __restrict__ yh)
{
    size_t row = blockIdx.x;
    int t = threadIdx.x;
    float4 v = reinterpret_cast<const float4*>(x + row * DD)[t];
    float ss = v.x * v.x + v.y * v.y + v.z * v.z + v.w * v.w;
#pragma unroll
    for (int o = 16; o > 0; o >>= 1) ss += __shfl_xor_sync(0xffffffffu, ss, o);
    __shared__ float sb[4];
    if ((t & 31) == 0) sb[t >> 5] = ss;
    __syncthreads();
    float tot = sb[0] + sb[1] + sb[2] + sb[3];
    float r = rsqrtf(tot * (1.0f / DD) + EPSF);
    hf2* out = reinterpret_cast<hf2*>(yh + row * DD + 4 * t);
    out[0] = __floats2half2_rn(v.x * r, v.y * r);
    out[1] = __floats2half2_rn(v.z * r, v.w * r);
}

__global__ void combine_rms_single()
{
    size_t row = blockIdx.x;
    int t = threadIdx.x;
    float4 a = reinterpret_cast<const float4*>(g_state + row * DD)[t];
    float4 b = reinterpret_cast<const float4*>(g_state + (row + (size_t)BATCH * SS) * DD)[t];
    float4 v = make_float4(0.5f * (a.x + b.x), 0.5f * (a.y + b.y),
                           0.5f * (a.z + b.z), 0.5f * (a.w + b.w));
    float ss = v.x * v.x + v.y * v.y + v.z * v.z + v.w * v.w;
#pragma unroll
    for (int o = 16; o > 0; o >>= 1) ss += __shfl_xor_sync(0xffffffffu, ss, o);
    __shared__ float sb[4];
    if ((t & 31) == 0) sb[t >> 5] = ss;
    __syncthreads();
    float tot = sb[0] + sb[1] + sb[2] + sb[3];
    float r = rsqrtf(tot * (1.0f / DD) + EPSF);
    hf2* out = reinterpret_cast<hf2*>(g_cmbh + row * DD + 4 * t);
    out[0] = __floats2half2_rn(v.x * r, v.y * r);
    out[1] = __floats2half2_rn(v.z * r, v.w * r);
}

__global__ void embed_kernel(const int* __restrict__ toks, const float* __restrict__ emb)
{
    size_t row = blockIdx.x;
    int t = threadIdx.x;
    int s = (int)(row & (SS - 1));
    int vb = (int)(row >> 11);
    int b = vb & 7, v = vb >> 3;
    int tok = toks[b * SS + s];
    const float4* src = reinterpret_cast<const float4*>(
        emb + ((size_t)v * NVOCAB + tok) * DD);
    reinterpret_cast<float4*>(g_state + row * DD)[t] = src[t];
}

// pack Wgu = [Wg|Wu], Wqkv = [Wq|Wk|Wv] (row-major 512 x 1536, fp16)
__global__ void pack_w(const float* __restrict__ Wg, const float* __restrict__ Wu,
                       const float* __restrict__ Wq, const float* __restrict__ Wk,
                       const float* __restrict__ Wv)
{
    int idx = blockIdx.x * blockDim.x + threadIdx.x;
    if (idx >= DD * 1536) return;
    int r = idx / 1536, c = idx % 1536;
    float a = (c < DD) ? Wg[r * DD + c] : Wu[r * (2 * DD) + (c - DD)];
    g_wgu[idx] = __float2half_rn(a);
    float q;
    if (c < DD)            q = Wq[r * DD + c];
    else if (c < 2 * DD)   q = Wk[r * DD + (c - DD)];
    else                   q = Wv[r * DD + (c - 2 * DD)];
    g_wqkv[idx] = __float2half_rn(q);
}

__global__ void convw(const float* __restrict__ s, hf* __restrict__ h, int n)
{
    int i = blockIdx.x * blockDim.x + threadIdx.x;
    if (i < n) h[i] = __float2half_rn(s[i]);
}

__global__ void zero_accf()
{
    size_t i = (size_t)blockIdx.x * blockDim.x + threadIdx.x;
    if (i < (size_t)VB * DD * DD) g_accf[i] = 0.f;
}

// ---------------- host launch ----------------
template <typename T>
static T* sym_addr(const void* sym)
{
    void* p = nullptr;
    cudaGetSymbolAddress(&p, sym);
    return (T*)p;
}

extern "C" void kernel_launch(void* const* d_in, const int* in_sizes, int n_in,
                              void* d_out, int out_size)
{
    const int*   toks = (const int*)d_in[0];
    const float* emb  = (const float*)d_in[1];
    const float* Wg   = (const float*)d_in[2];
    const float* Wu   = (const float*)d_in[3];
    const float* Wd   = (const float*)d_in[4];
    const float* Wq   = (const float*)d_in[5];
    const float* Wk   = (const float*)d_in[6];
    const float* Wv   = (const float*)d_in[7];
    const float* Wo   = (const float*)d_in[8];
    const float* Wlm  = (const float*)d_in[9];
    float* out = (float*)d_out;

    float* state = sym_addr<float>(g_state);
    float* gate  = sym_addr<float>(g_gate);
    float* accf  = sym_addr<float>(g_accf);
    hf* nh = sym_addr<hf>(g_nh);
    hf* Hh = sym_addr<hf>(g_Hh);   hf* Hl = sym_addr<hf>(g_Hl);
    hf* qh = sym_addr<hf>(g_qh);   hf* ql = sym_addr<hf>(g_ql);
    hf* kh = sym_addr<hf>(g_kh);   hf* kl = sym_addr<hf>(g_kl);
    hf* vh = sym_addr<hf>(g_vh);
    hf* acch = sym_addr<hf>(g_acch); hf* accl = sym_addr<hf>(g_accl);
    hf* awh = sym_addr<hf>(g_awh);
    hf* cmbh = sym_addr<hf>(g_cmbh);
    hf* wgu = sym_addr<hf>(g_wgu);   hf* wqkv = sym_addr<hf>(g_wqkv);
    hf* wd = sym_addr<hf>(g_wd);     hf* wo = sym_addr<hf>(g_wo);
    hf* wlm = sym_addr<hf>(g_wlm);

    const int SMEM_NN_D = STAGES * (2 * GBM * ASTR + GBK * BSTR) * 2;   // dual A
    const int SMEM_NN_S = STAGES * (GBM * ASTR + GBK * BSTR) * 2;       // single A
    const int SMEM_TN   = STAGES * (3 * GBK * BSTR) * 2;

    cudaFuncSetAttribute((const void*)gemm<EPI_GU,     false, false>, cudaFuncAttributeMaxDynamicSharedMemorySize, SMEM_NN_S);
    cudaFuncSetAttribute((const void*)gemm<EPI_GATED,  false, true >, cudaFuncAttributeMaxDynamicSharedMemorySize, SMEM_NN_D);
    cudaFuncSetAttribute((const void*)gemm<EPI_QKV,    false, false>, cudaFuncAttributeMaxDynamicSharedMemorySize, SMEM_NN_S);
    cudaFuncSetAttribute((const void*)gemm<EPI_ACC,    true,  true >, cudaFuncAttributeMaxDynamicSharedMemorySize, SMEM_TN);
    cudaFuncSetAttribute((const void*)gemm<EPI_PLANES, false, true >, cudaFuncAttributeMaxDynamicSharedMemorySize, SMEM_NN_D);
    cudaFuncSetAttribute((const void*)gemm<EPI_ADD,    false, true >, cudaFuncAttributeMaxDynamicSharedMemorySize, SMEM_NN_D);
    cudaFuncSetAttribute((const void*)gemm<EPI_STORE,  false, false>, cudaFuncAttributeMaxDynamicSharedMemorySize, SMEM_NN_S);

    const float inv_s      = 1.0f / (float)SS;
    const float inv_sqrt_d = 1.0f / sqrtf((float)DD);
    const size_t tok_str = (size_t)SS * DD;
    const size_t acc_str = (size_t)DD * DD;

    embed_kernel<<<NTOK, 128>>>(toks, emb);
    pack_w<<<(DD * 1536 + 255) / 256, 256>>>(Wg, Wu, Wq, Wk, Wv);
    convw<<<(2 * DD * DD + 255) / 256, 256>>>(Wd, wd, 2 * DD * DD);
    convw<<<(DD * DD + 255) / 256, 256>>>(Wo, wo, DD * DD);
    convw<<<(DD * NVOCAB + 255) / 256, 256>>>(Wlm, wlm, DD * NVOCAB);
    zero_accf<<<(int)(((size_t)VB * DD * DD + 255) / 256), 256>>>();

    for (int step = 0; step < NSTEPS; step++) {
        rms_single<<<NTOK, 128>>>(state, nh);
        // GU = n @ [Wg|Wu]: gate=sigmoid f32, H=gelu planes  (single-A)
        gemm<EPI_GU, false, false><<<dim3(1536 / GBN, NTOK / GBM, 1), 256, SMEM_NN_S>>>(
            NTOK, 1536, DD, nh, nullptr, DD, 0, wgu, 1536, 0,
            1.f, 0.f, gate, DD, 0, Hh, Hl, 1024, 0,
            nullptr, nullptr, nullptr, nullptr);
        // state += gate * (H @ Wd)  (dual-A)
        gemm<EPI_GATED, false, true><<<dim3(DD / GBN, NTOK / GBM, 1), 256, SMEM_NN_D>>>(
            NTOK, DD, 2 * DD, Hh, Hl, 2 * DD, 0, wd, DD, 0,
            1.f, 0.f, state, DD, 0, nullptr, nullptr, 0, 0,
            nullptr, nullptr, nullptr, gate);
        rms_single<<<NTOK, 128>>>(state, nh);
        // QKV = n2 @ [Wq|Wk|Wv]: phi on q,k; v hi only  (single-A)
        gemm<EPI_QKV, false, false><<<dim3(1536 / GBN, NTOK / GBM, 1), 256, SMEM_NN_S>>>(
            NTOK, 1536, DD, nh, nullptr, DD, 0, wqkv, 1536, 0,
            1.f, 0.f, nullptr, 0, 0, qh, ql, DD, 0,
            kh, kl, vh, nullptr);
        // acc = DECAY*acc + inv_s * k^T @ v (batched); write acc planes  (dual-A)
        gemm<EPI_ACC, true, true><<<dim3(DD / GBN, DD / GBM, VB), 256, SMEM_TN>>>(
            DD, DD, SS, kh, kl, DD, tok_str, vh, DD, tok_str,
            inv_s, DECAYF, accf, DD, acc_str, acch, accl, DD, acc_str,
            nullptr, nullptr, nullptr, nullptr);
        // accWo = acc @ Wo -> hi-only plane (batched)  (dual-A)
        gemm<EPI_PLANES, false, true><<<dim3(DD / GBN, DD / GBM, VB), 256, SMEM_NN_D>>>(
            DD, DD, DD, acch, accl, DD, acc_str, wo, DD, 0,
            1.f, 0.f, nullptr, 0, 0, awh, nullptr, DD, acc_str,
            nullptr, nullptr, nullptr, nullptr);
        // state += inv_sqrt_d * q @ accWo (batched)  (dual-A)
        gemm<EPI_ADD, false, true><<<dim3(DD / GBN, SS / GBM, VB), 256, SMEM_NN_D>>>(
            SS, DD, DD, qh, ql, DD, tok_str, awh, DD, acc_str,
            inv_sqrt_d, 0.f, state, DD, tok_str, nullptr, nullptr, 0, 0,
            nullptr, nullptr, nullptr, nullptr);
    }

    combine_rms_single<<<BATCH * SS, 128>>>();
    gemm<EPI_STORE, false, false><<<dim3(NVOCAB / GBN, (BATCH * SS) / GBM, 1), 256, SMEM_NN_S>>>(
        BATCH * SS, NVOCAB, DD, cmbh, nullptr, DD, 0, wlm, NVOCAB, 0,
        1.f, 0.f, out, NVOCAB, 0, nullptr, nullptr, 0, 0,
        nullptr, nullptr, nullptr, nullptr);
    (void)in_sizes; (void)n_in; (void)out_size;
}

// round 8
// speedup vs baseline: 5.3074x; 1.3334x over previous
#include <cuda_runtime.h>
#include <cuda_fp16.h>
#include <math.h>
#include <stdint.h>

// ---------------- problem constants ----------------
#define DD     512
#define SS     2048
#define BATCH  8
#define VB     16
#define NTOK   32768
#define NVOCAB 8192
#define NSTEPS 16
#define DECAYF 0.999f
#define EPSF   1e-6f

typedef __half hf;
typedef __half2 hf2;

// ---------------- scratch (static device globals; allocation-free) ----------------
__device__ float g_state[(size_t)NTOK * DD];
__device__ float g_gate [(size_t)NTOK * DD];
__device__ float g_accf [(size_t)VB * DD * DD];

__device__ hf g_nh[(size_t)NTOK * DD];                    // rms planes (single)
__device__ hf g_Hh[(size_t)NTOK * 2 * DD];                // gelu H (single)
__device__ hf g_qh[(size_t)NTOK * DD];                    // phi(q) (single)
__device__ hf g_kh[(size_t)NTOK * DD],  g_kl[(size_t)NTOK * DD];  // phi(k) dual (ACC A)
__device__ hf g_vh[(size_t)NTOK * DD];                    // v (single, B side)
__device__ hf g_acch[(size_t)VB * DD * DD];               // acc (single)
__device__ hf g_awh [(size_t)VB * DD * DD];               // accWo (single, B side)
__device__ hf g_cmbh[(size_t)BATCH * SS * DD];            // combined (single)

// weights: single fp16 plane (B side)
__device__ hf g_wgu [DD * 1536];
__device__ hf g_wqkv[DD * 1536];
__device__ hf g_wd  [2 * DD * DD];
__device__ hf g_wo  [DD * DD];
__device__ hf g_wlm [DD * NVOCAB];

// ---------------- helpers ----------------
__device__ __forceinline__ void split1(float x, hf& h, hf& l)
{
    h = __float2half_rn(x);
    l = __float2half_rn(x - __half2float(h));
}
__device__ __forceinline__ void splitstore(hf* __restrict__ Ph, hf* __restrict__ Pl,
                                           size_t off, float x, float y)
{
    hf hx, lx, hy, ly;
    split1(x, hx, lx); split1(y, hy, ly);
    *reinterpret_cast<hf2*>(Ph + off) = __halves2half2(hx, hy);
    *reinterpret_cast<hf2*>(Pl + off) = __halves2half2(lx, ly);
}
__device__ __forceinline__ float sigf(float x) { return 1.0f / (1.0f + expf(-x)); }
__device__ __forceinline__ float geluf(float x)
{ return 0.5f * x * (1.0f + erff(x * 0.70710678118654752f)); }
__device__ __forceinline__ float phif(float x) { return (x > 0.f) ? x + 1.f : expf(x); }

__device__ __forceinline__ void cp16(void* dst, const void* src)
{
    uint32_t d = (uint32_t)__cvta_generic_to_shared(dst);
    asm volatile("cp.async.cg.shared.global [%0], [%1], 16;" :: "r"(d), "l"(src));
}
__device__ __forceinline__ void cp_commit() { asm volatile("cp.async.commit_group;" ::: "memory"); }
__device__ __forceinline__ void cp_wait1()  { asm volatile("cp.async.wait_group 1;" ::: "memory"); }

__device__ __forceinline__ void ldsm4(uint32_t r[4], const void* p)
{
    uint32_t a = (uint32_t)__cvta_generic_to_shared(p);
    asm volatile("ldmatrix.sync.aligned.m8n8.x4.shared.b16 {%0,%1,%2,%3}, [%4];"
                 : "=r"(r[0]), "=r"(r[1]), "=r"(r[2]), "=r"(r[3]) : "r"(a));
}
__device__ __forceinline__ void ldsm4t(uint32_t r[4], const void* p)
{
    uint32_t a = (uint32_t)__cvta_generic_to_shared(p);
    asm volatile("ldmatrix.sync.aligned.m8n8.x4.trans.shared.b16 {%0,%1,%2,%3}, [%4];"
                 : "=r"(r[0]), "=r"(r[1]), "=r"(r[2]), "=r"(r[3]) : "r"(a));
}
__device__ __forceinline__ void mma16816(float c[4], const uint32_t a[4], const uint32_t b[2])
{
    asm volatile(
        "mma.sync.aligned.m16n8k16.row.col.f32.f16.f16.f32 "
        "{%0,%1,%2,%3}, {%4,%5,%6,%7}, {%8,%9}, {%0,%1,%2,%3};"
        : "+f"(c[0]), "+f"(c[1]), "+f"(c[2]), "+f"(c[3])
        : "r"(a[0]), "r"(a[1]), "r"(a[2]), "r"(a[3]), "r"(b[0]), "r"(b[1]));
}

// ---------------- pipelined fp16 tensor-core GEMM ----------------
// ALO=true : A = hi+lo planes (2 mma per product)
// ALO=false: A = hi plane only (1 mma per product)
#define GBM 128
#define GBN 128
#define GBK 32
#define ASTR 40     // smem A row stride (elems) for NN layout [m][k]
#define BSTR 136    // smem row stride (elems) for [k][n] / [k][m] layouts
#define STAGES 3

enum { EPI_STORE = 0, EPI_GU = 1, EPI_GATED = 2, EPI_QKV = 3,
       EPI_ACC = 4, EPI_PLANES = 5, EPI_ADD = 6 };

template <int EPI, bool TRANSA, bool ALO>
__global__ void __launch_bounds__(256, ALO ? 1 : 2) gemm(
    int M, int N, int K,
    const hf* __restrict__ Ah, const hf* __restrict__ Al, int lda, size_t sA,
    const hf* __restrict__ Bh, int ldb, size_t sB,
    float alpha, float beta,
    float* __restrict__ C, int ldc, size_t sC,
    hf* __restrict__ Ph, hf* __restrict__ Pl, int ldp, size_t sP,
    hf* __restrict__ P2h, hf* __restrict__ P2l, hf* __restrict__ P3h,
    const float* __restrict__ Gate)
{
    const int z = blockIdx.z;
    Ah += (size_t)z * sA;
    if (ALO) Al += (size_t)z * sA;
    Bh += (size_t)z * sB;
    if (C)  C  += (size_t)z * sC;
    if (Ph) { Ph += (size_t)z * sP; if (Pl) Pl += (size_t)z * sP; }

    constexpr int NPL  = ALO ? 2 : 1;
    constexpr int A_PL = TRANSA ? (GBK * BSTR) : (GBM * ASTR);
    constexpr int B_PL = GBK * BSTR;
    constexpr int STG  = NPL * A_PL + B_PL;
    extern __shared__ __align__(16) hf sm[];

    const int tid = threadIdx.x, lane = tid & 31, warp = tid >> 5;
    const int wm = warp & 3, wn = warp >> 2;
    const size_t m_blk = (size_t)blockIdx.y * GBM;
    const size_t n_blk = (size_t)blockIdx.x * GBN;
    const int KT = K / GBK;

    float acc[2][8][4];
#pragma unroll
    for (int mi = 0; mi < 2; mi++)
#pragma unroll
        for (int ni = 0; ni < 8; ni++)
#pragma unroll
            for (int v = 0; v < 4; v++) acc[mi][ni][v] = 0.f;

    auto issue = [&](int kt) {
        if (kt >= KT) { cp_commit(); return; }
        const int st = kt % STAGES;
        const int k0 = kt * GBK;
        hf* dA = sm + st * STG;
        hf* dB = dA + NPL * A_PL;
        // A: NPL planes, 512 chunks each
#pragma unroll
        for (int i = 0; i < 2 * NPL; i++) {
            int ch = tid + i * 256;
            int pl = ALO ? (ch >> 9) : 0;
            const hf* sp = (ALO && pl) ? Al : Ah;
            if (!TRANSA) {
                int r = (ch >> 2) & 127, kc = (ch & 3) * 8;
                cp16(dA + pl * A_PL + r * ASTR + kc,
                     sp + (m_blk + r) * (size_t)lda + k0 + kc);
            } else {
                int r = (ch & 511) >> 4, c = (ch & 15) * 8;
                cp16(dA + pl * A_PL + r * BSTR + c,
                     sp + (size_t)(k0 + r) * lda + m_blk + c);
            }
        }
        // B: 1 plane
#pragma unroll
        for (int i = 0; i < 2; i++) {
            int ch = tid + i * 256;
            int r = ch >> 4, c = (ch & 15) * 8;
            cp16(dB + r * BSTR + c,
                 Bh + (size_t)(k0 + r) * ldb + n_blk + c);
        }
        cp_commit();
    };

    issue(0);
    issue(1);

    for (int kt = 0; kt < KT; kt++) {
        cp_wait1();
        __syncthreads();
        issue(kt + 2);

        const hf* Ahs = sm + (kt % STAGES) * STG;
        const hf* Als = Ahs + A_PL;
        const hf* Bhs = Ahs + NPL * A_PL;

#pragma unroll
        for (int ks = 0; ks < 2; ks++) {
            const int kk = ks * 16;
            uint32_t ah[2][4], al[2][4];
            if (!TRANSA) {
                const int ar = lane & 15;
                const int ac = kk + (lane >> 4) * 8;
#pragma unroll
                for (int mi = 0; mi < 2; mi++) {
                    ldsm4(ah[mi], Ahs + (size_t)(wm * 32 + mi * 16 + ar) * ASTR + ac);
                    if (ALO)
                        ldsm4(al[mi], Als + (size_t)(wm * 32 + mi * 16 + ar) * ASTR + ac);
                }
            } else {
                const int q = lane >> 3;
                const int arow = kk + (q >> 1) * 8 + (lane & 7);
#pragma unroll
                for (int mi = 0; mi < 2; mi++) {
                    const int acol = wm * 32 + mi * 16 + (q & 1) * 8;
                    ldsm4t(ah[mi], Ahs + (size_t)arow * BSTR + acol);
                    if (ALO)
                        ldsm4t(al[mi], Als + (size_t)arow * BSTR + acol);
                }
            }
            uint32_t bh[8][2];
            const int q = lane >> 3;
            const int br = kk + (q & 1) * 8 + (lane & 7);
#pragma unroll
            for (int nt = 0; nt < 4; nt++) {
                const int bc = wn * 64 + nt * 16 + (q >> 1) * 8;
                uint32_t r[4];
                ldsm4t(r, Bhs + (size_t)br * BSTR + bc);
                bh[2 * nt][0] = r[0]; bh[2 * nt][1] = r[1];
                bh[2 * nt + 1][0] = r[2]; bh[2 * nt + 1][1] = r[3];
            }
#pragma unroll
            for (int mi = 0; mi < 2; mi++)
#pragma unroll
                for (int ni = 0; ni < 8; ni++) {
                    mma16816(acc[mi][ni], ah[mi], bh[ni]);
                    if (ALO) mma16816(acc[mi][ni], al[mi], bh[ni]);
                }
        }
    }

    // ---- epilogue ----
    const int g = lane >> 2, tg = lane & 3;
#pragma unroll
    for (int mi = 0; mi < 2; mi++) {
        size_t rr[2];
        rr[0] = m_blk + wm * 32 + mi * 16 + g;
        rr[1] = rr[0] + 8;
#pragma unroll
        for (int ni = 0; ni < 8; ni++) {
            size_t col = n_blk + wn * 64 + ni * 8 + tg * 2;
#pragma unroll
            for (int h = 0; h < 2; h++) {
                size_t row = rr[h];
                float x = alpha * acc[mi][ni][2 * h];
                float y = alpha * acc[mi][ni][2 * h + 1];
                if (EPI == EPI_STORE) {
                    *reinterpret_cast<float2*>(C + row * ldc + col) = make_float2(x, y);
                } else if (EPI == EPI_ADD) {
                    float2* p = reinterpret_cast<float2*>(C + row * ldc + col);
                    float2 c = *p; c.x += x; c.y += y; *p = c;
                } else if (EPI == EPI_GATED) {
                    float2* p = reinterpret_cast<float2*>(C + row * ldc + col);
                    float2 gg = *reinterpret_cast<const float2*>(Gate + row * 512 + col);
                    float2 c = *p; c.x += gg.x * x; c.y += gg.y * y; *p = c;
                } else if (EPI == EPI_GU) {
                    if (col < 512)
                        *reinterpret_cast<float2*>(C + row * 512 + col) =
                            make_float2(sigf(x), sigf(y));
                    else
                        *reinterpret_cast<hf2*>(Ph + row * (size_t)1024 + (col - 512)) =
                            __floats2half2_rn(geluf(x), geluf(y));
                } else if (EPI == EPI_QKV) {
                    const int reg = (int)(col >> 9);
                    if (reg == 0)
                        *reinterpret_cast<hf2*>(Ph + row * (size_t)512 + (col & 511)) =
                            __floats2half2_rn(phif(x), phif(y));
                    else if (reg == 1)
                        splitstore(P2h, P2l, row * (size_t)512 + (col & 511),
                                   phif(x), phif(y));
                    else
                        *reinterpret_cast<hf2*>(P3h + row * (size_t)512 + (col & 511)) =
                            __floats2half2_rn(x, y);
                } else if (EPI == EPI_ACC) {
                    float2* p = reinterpret_cast<float2*>(C + row * ldc + col);
                    float2 c = *p;
                    c.x = beta * c.x + x; c.y = beta * c.y + y;
                    *p = c;
                    *reinterpret_cast<hf2*>(Ph + row * (size_t)ldp + col) =
                        __floats2half2_rn(c.x, c.y);
                } else { // EPI_PLANES: hi-only store
                    *reinterpret_cast<hf2*>(Ph + row * (size_t)ldp + col) =
                        __floats2half2_rn(x, y);
                }
            }
        }
    }
}

// ---------------- elementwise / norm kernels ----------------
__global__ void rms_single(const float* __restrict__ x, hf* __restrict__ yh)
{
    size_t row = blockIdx.x;
    int t = threadIdx.x;
    float4 v = reinterpret_cast<const float4*>(x + row * DD)[t];
    float ss = v.x * v.x + v.y * v.y + v.z * v.z + v.w * v.w;
#pragma unroll
    for (int o = 16; o > 0; o >>= 1) ss += __shfl_xor_sync(0xffffffffu, ss, o);
    __shared__ float sb[4];
    if ((t & 31) == 0) sb[t >> 5] = ss;
    __syncthreads();
    float tot = sb[0] + sb[1] + sb[2] + sb[3];
    float r = rsqrtf(tot * (1.0f / DD) + EPSF);
    hf2* out = reinterpret_cast<hf2*>(yh + row * DD + 4 * t);
    out[0] = __floats2half2_rn(v.x * r, v.y * r);
    out[1] = __floats2half2_rn(v.z * r, v.w * r);
}

__global__ void combine_rms_single()
{
    size_t row = blockIdx.x;
    int t = threadIdx.x;
    float4 a = reinterpret_cast<const float4*>(g_state + row * DD)[t];
    float4 b = reinterpret_cast<const float4*>(g_state + (row + (size_t)BATCH * SS) * DD)[t];
    float4 v = make_float4(0.5f * (a.x + b.x), 0.5f * (a.y + b.y),
                           0.5f * (a.z + b.z), 0.5f * (a.w + b.w));
    float ss = v.x * v.x + v.y * v.y + v.z * v.z + v.w * v.w;
#pragma unroll
    for (int o = 16; o > 0; o >>= 1) ss += __shfl_xor_sync(0xffffffffu, ss, o);
    __shared__ float sb[4];
    if ((t & 31) == 0) sb[t >> 5] = ss;
    __syncthreads();
    float tot = sb[0] + sb[1] + sb[2] + sb[3];
    float r = rsqrtf(tot * (1.0f / DD) + EPSF);
    hf2* out = reinterpret_cast<hf2*>(g_cmbh + row * DD + 4 * t);
    out[0] = __floats2half2_rn(v.x * r, v.y * r);
    out[1] = __floats2half2_rn(v.z * r, v.w * r);
}

__global__ void embed_kernel(const int* __restrict__ toks, const float* __restrict__ emb)
{
    size_t row = blockIdx.x;
    int t = threadIdx.x;
    int s = (int)(row & (SS - 1));
    int vb = (int)(row >> 11);
    int b = vb & 7, v = vb >> 3;
    int tok = toks[b * SS + s];
    const float4* src = reinterpret_cast<const float4*>(
        emb + ((size_t)v * NVOCAB + tok) * DD);
    reinterpret_cast<float4*>(g_state + row * DD)[t] = src[t];
}

// pack Wgu = [Wg|Wu], Wqkv = [Wq|Wk|Wv] (row-major 512 x 1536, fp16)
__global__ void pack_w(const float* __restrict__ Wg, const float* __restrict__ Wu,
                       const float* __restrict__ Wq, const float* __restrict__ Wk,
                       const float* __restrict__ Wv)
{
    int idx = blockIdx.x * blockDim.x + threadIdx.x;
    if (idx >= DD * 1536) return;
    int r = idx / 1536, c = idx % 1536;
    float a = (c < DD) ? Wg[r * DD + c] : Wu[r * (2 * DD) + (c - DD)];
    g_wgu[idx] = __float2half_rn(a);
    float q;
    if (c < DD)            q = Wq[r * DD + c];
    else if (c < 2 * DD)   q = Wk[r * DD + (c - DD)];
    else                   q = Wv[r * DD + (c - 2 * DD)];
    g_wqkv[idx] = __float2half_rn(q);
}

__global__ void convw(const float* __restrict__ s, hf* __restrict__ h, int n)
{
    int i = blockIdx.x * blockDim.x + threadIdx.x;
    if (i < n) h[i] = __float2half_rn(s[i]);
}

__global__ void zero_accf()
{
    size_t i = (size_t)blockIdx.x * blockDim.x + threadIdx.x;
    if (i < (size_t)VB * DD * DD) g_accf[i] = 0.f;
}

// ---------------- host launch ----------------
template <typename T>
static T* sym_addr(const void* sym)
{
    void* p = nullptr;
    cudaGetSymbolAddress(&p, sym);
    return (T*)p;
}

extern "C" void kernel_launch(void* const* d_in, const int* in_sizes, int n_in,
                              void* d_out, int out_size)
{
    const int*   toks = (const int*)d_in[0];
    const float* emb  = (const float*)d_in[1];
    const float* Wg   = (const float*)d_in[2];
    const float* Wu   = (const float*)d_in[3];
    const float* Wd   = (const float*)d_in[4];
    const float* Wq   = (const float*)d_in[5];
    const float* Wk   = (const float*)d_in[6];
    const float* Wv   = (const float*)d_in[7];
    const float* Wo   = (const float*)d_in[8];
    const float* Wlm  = (const float*)d_in[9];
    float* out = (float*)d_out;

    float* state = sym_addr<float>(g_state);
    float* gate  = sym_addr<float>(g_gate);
    float* accf  = sym_addr<float>(g_accf);
    hf* nh = sym_addr<hf>(g_nh);
    hf* Hh = sym_addr<hf>(g_Hh);
    hf* qh = sym_addr<hf>(g_qh);
    hf* kh = sym_addr<hf>(g_kh);   hf* kl = sym_addr<hf>(g_kl);
    hf* vh = sym_addr<hf>(g_vh);
    hf* acch = sym_addr<hf>(g_acch);
    hf* awh = sym_addr<hf>(g_awh);
    hf* cmbh = sym_addr<hf>(g_cmbh);
    hf* wgu = sym_addr<hf>(g_wgu);   hf* wqkv = sym_addr<hf>(g_wqkv);
    hf* wd = sym_addr<hf>(g_wd);     hf* wo = sym_addr<hf>(g_wo);
    hf* wlm = sym_addr<hf>(g_wlm);

    const int SMEM_NN_S = STAGES * (GBM * ASTR + GBK * BSTR) * 2;       // single A
    const int SMEM_TN   = STAGES * (3 * GBK * BSTR) * 2;                // dual A (TN)

    cudaFuncSetAttribute((const void*)gemm<EPI_GU,     false, false>, cudaFuncAttributeMaxDynamicSharedMemorySize, SMEM_NN_S);
    cudaFuncSetAttribute((const void*)gemm<EPI_GATED,  false, false>, cudaFuncAttributeMaxDynamicSharedMemorySize, SMEM_NN_S);
    cudaFuncSetAttribute((const void*)gemm<EPI_QKV,    false, false>, cudaFuncAttributeMaxDynamicSharedMemorySize, SMEM_NN_S);
    cudaFuncSetAttribute((const void*)gemm<EPI_ACC,    true,  true >, cudaFuncAttributeMaxDynamicSharedMemorySize, SMEM_TN);
    cudaFuncSetAttribute((const void*)gemm<EPI_PLANES, false, false>, cudaFuncAttributeMaxDynamicSharedMemorySize, SMEM_NN_S);
    cudaFuncSetAttribute((const void*)gemm<EPI_ADD,    false, false>, cudaFuncAttributeMaxDynamicSharedMemorySize, SMEM_NN_S);
    cudaFuncSetAttribute((const void*)gemm<EPI_STORE,  false, false>, cudaFuncAttributeMaxDynamicSharedMemorySize, SMEM_NN_S);

    const float inv_s      = 1.0f / (float)SS;
    const float inv_sqrt_d = 1.0f / sqrtf((float)DD);
    const size_t tok_str = (size_t)SS * DD;
    const size_t acc_str = (size_t)DD * DD;

    embed_kernel<<<NTOK, 128>>>(toks, emb);
    pack_w<<<(DD * 1536 + 255) / 256, 256>>>(Wg, Wu, Wq, Wk, Wv);
    convw<<<(2 * DD * DD + 255) / 256, 256>>>(Wd, wd, 2 * DD * DD);
    convw<<<(DD * DD + 255) / 256, 256>>>(Wo, wo, DD * DD);
    convw<<<(DD * NVOCAB + 255) / 256, 256>>>(Wlm, wlm, DD * NVOCAB);
    zero_accf<<<(int)(((size_t)VB * DD * DD + 255) / 256), 256>>>();

    for (int step = 0; step < NSTEPS; step++) {
        rms_single<<<NTOK, 128>>>(state, nh);
        // GU = n @ [Wg|Wu]: gate=sigmoid f32, H=gelu hi-only  (single-A)
        gemm<EPI_GU, false, false><<<dim3(1536 / GBN, NTOK / GBM, 1), 256, SMEM_NN_S>>>(
            NTOK, 1536, DD, nh, nullptr, DD, 0, wgu, 1536, 0,
            1.f, 0.f, gate, DD, 0, Hh, nullptr, 1024, 0,
            nullptr, nullptr, nullptr, nullptr);
        // state += gate * (H @ Wd)  (single-A)
        gemm<EPI_GATED, false, false><<<dim3(DD / GBN, NTOK / GBM, 1), 256, SMEM_NN_S>>>(
            NTOK, DD, 2 * DD, Hh, nullptr, 2 * DD, 0, wd, DD, 0,
            1.f, 0.f, state, DD, 0, nullptr, nullptr, 0, 0,
            nullptr, nullptr, nullptr, gate);
        rms_single<<<NTOK, 128>>>(state, nh);
        // QKV = n2 @ [Wq|Wk|Wv]: q hi-only, k dual planes, v hi-only  (single-A)
        gemm<EPI_QKV, false, false><<<dim3(1536 / GBN, NTOK / GBM, 1), 256, SMEM_NN_S>>>(
            NTOK, 1536, DD, nh, nullptr, DD, 0, wqkv, 1536, 0,
            1.f, 0.f, nullptr, 0, 0, qh, nullptr, DD, 0,
            kh, kl, vh, nullptr);
        // acc = DECAY*acc + inv_s * k^T @ v (batched); acc hi plane  (dual-A, protected)
        gemm<EPI_ACC, true, true><<<dim3(DD / GBN, DD / GBM, VB), 256, SMEM_TN>>>(
            DD, DD, SS, kh, kl, DD, tok_str, vh, DD, tok_str,
            inv_s, DECAYF, accf, DD, acc_str, acch, nullptr, DD, acc_str,
            nullptr, nullptr, nullptr, nullptr);
        // accWo = acc @ Wo -> hi-only plane (batched)  (single-A)
        gemm<EPI_PLANES, false, false><<<dim3(DD / GBN, DD / GBM, VB), 256, SMEM_NN_S>>>(
            DD, DD, DD, acch, nullptr, DD, acc_str, wo, DD, 0,
            1.f, 0.f, nullptr, 0, 0, awh, nullptr, DD, acc_str,
            nullptr, nullptr, nullptr, nullptr);
        // state += inv_sqrt_d * q @ accWo (batched)  (single-A)
        gemm<EPI_ADD, false, false><<<dim3(DD / GBN, SS / GBM, VB), 256, SMEM_NN_S>>>(
            SS, DD, DD, qh, nullptr, DD, tok_str, awh, DD, acc_str,
            inv_sqrt_d, 0.f, state, DD, tok_str, nullptr, nullptr, 0, 0,
            nullptr, nullptr, nullptr, nullptr);
    }

    combine_rms_single<<<BATCH * SS, 128>>>();
    gemm<EPI_STORE, false, false><<<dim3(NVOCAB / GBN, (BATCH * SS) / GBM, 1), 256, SMEM_NN_S>>>(
        BATCH * SS, NVOCAB, DD, cmbh, nullptr, DD, 0, wlm, NVOCAB, 0,
        1.f, 0.f, out, NVOCAB, 0, nullptr, nullptr, 0, 0,
        nullptr, nullptr, nullptr, nullptr);
    (void)in_sizes; (void)n_in; (void)out_size;
}

// round 9
// speedup vs baseline: 5.7945x; 1.0918x over previous
#include <cuda_runtime.h>
#include <cuda_fp16.h>
#include <math.h>
#include <stdint.h>

// ---------------- problem constants ----------------
#define DD     512
#define SS     2048
#define BATCH  8
#define VB     16
#define NTOK   32768
#define NVOCAB 8192
#define NSTEPS 16
#define DECAYF 0.999f
#define EPSF   1e-6f

typedef __half hf;
typedef __half2 hf2;

// ---------------- scratch (static device globals; allocation-free) ----------------
__device__ float g_state[(size_t)NTOK * DD];
__device__ float g_accf [(size_t)VB * DD * DD];           // f32 master accumulator

__device__ hf g_gateh[(size_t)NTOK * DD];                 // sigmoid gate (fp16)
__device__ hf g_nh[(size_t)NTOK * DD];                    // rms(state) (single)
__device__ hf g_Hh[(size_t)NTOK * 2 * DD];                // gelu H (single)
__device__ hf g_qh[(size_t)NTOK * DD];                    // phi(q) (single)
__device__ hf g_kh[(size_t)NTOK * DD];                    // phi(k) (single)
__device__ hf g_vh[(size_t)NTOK * DD];                    // v (single)
__device__ hf g_acch[(size_t)VB * DD * DD];               // acc hi plane
__device__ hf g_awh [(size_t)VB * DD * DD];               // accWo (single)
__device__ hf g_cmbh[(size_t)BATCH * SS * DD];            // combined (single)

// weights: single fp16 plane (B side)
__device__ hf g_wgu [DD * 1536];
__device__ hf g_wqkv[DD * 1536];
__device__ hf g_wd  [2 * DD * DD];
__device__ hf g_wo  [DD * DD];
__device__ hf g_wlm [DD * NVOCAB];

// ---------------- helpers ----------------
__device__ __forceinline__ float sigf(float x) { return 1.0f / (1.0f + expf(-x)); }
__device__ __forceinline__ float geluf(float x)
{ return 0.5f * x * (1.0f + erff(x * 0.70710678118654752f)); }
__device__ __forceinline__ float phif(float x) { return (x > 0.f) ? x + 1.f : expf(x); }

__device__ __forceinline__ void cp16(void* dst, const void* src)
{
    uint32_t d = (uint32_t)__cvta_generic_to_shared(dst);
    asm volatile("cp.async.cg.shared.global [%0], [%1], 16;" :: "r"(d), "l"(src));
}
__device__ __forceinline__ void cp_commit() { asm volatile("cp.async.commit_group;" ::: "memory"); }
__device__ __forceinline__ void cp_wait1()  { asm volatile("cp.async.wait_group 1;" ::: "memory"); }

__device__ __forceinline__ void ldsm4(uint32_t r[4], const void* p)
{
    uint32_t a = (uint32_t)__cvta_generic_to_shared(p);
    asm volatile("ldmatrix.sync.aligned.m8n8.x4.shared.b16 {%0,%1,%2,%3}, [%4];"
                 : "=r"(r[0]), "=r"(r[1]), "=r"(r[2]), "=r"(r[3]) : "r"(a));
}
__device__ __forceinline__ void ldsm4t(uint32_t r[4], const void* p)
{
    uint32_t a = (uint32_t)__cvta_generic_to_shared(p);
    asm volatile("ldmatrix.sync.aligned.m8n8.x4.trans.shared.b16 {%0,%1,%2,%3}, [%4];"
                 : "=r"(r[0]), "=r"(r[1]), "=r"(r[2]), "=r"(r[3]) : "r"(a));
}
__device__ __forceinline__ void mma16816(float c[4], const uint32_t a[4], const uint32_t b[2])
{
    asm volatile(
        "mma.sync.aligned.m16n8k16.row.col.f32.f16.f16.f32 "
        "{%0,%1,%2,%3}, {%4,%5,%6,%7}, {%8,%9}, {%0,%1,%2,%3};"
        : "+f"(c[0]), "+f"(c[1]), "+f"(c[2]), "+f"(c[3])
        : "r"(a[0]), "r"(a[1]), "r"(a[2]), "r"(a[3]), "r"(b[0]), "r"(b[1]));
}

// ---------------- pipelined fp16 (single-product) tensor-core GEMM ----------------
#define GBM 128
#define GBN 128
#define GBK 32
#define ASTR 40     // smem A row stride (elems) for NN layout [m][k]
#define BSTR 136    // smem row stride (elems) for [k][n] / [k][m] layouts
#define STAGES 3

enum { EPI_STORE = 0, EPI_GU = 1, EPI_GATED = 2, EPI_QKV = 3,
       EPI_ACC = 4, EPI_PLANES = 5, EPI_ADD = 6 };

template <int EPI, bool TRANSA>
__global__ void __launch_bounds__(256, 2) gemm(
    int M, int N, int K,
    const hf* __restrict__ Ah, int lda, size_t sA,
    const hf* __restrict__ Bh, int ldb, size_t sB,
    float alpha, float beta,
    float* __restrict__ C, int ldc, size_t sC,
    hf* __restrict__ Ph, int ldp, size_t sP,
    hf* __restrict__ P2h, hf* __restrict__ P3h,
    const hf* __restrict__ Gate)
{
    const int z = blockIdx.z;
    Ah += (size_t)z * sA;
    Bh += (size_t)z * sB;
    if (C)  C  += (size_t)z * sC;
    if (Ph) Ph += (size_t)z * sP;

    constexpr int A_PL = TRANSA ? (GBK * BSTR) : (GBM * ASTR);
    constexpr int B_PL = GBK * BSTR;
    constexpr int STG  = A_PL + B_PL;
    extern __shared__ __align__(16) hf sm[];

    const int tid = threadIdx.x, lane = tid & 31, warp = tid >> 5;
    const int wm = warp & 3, wn = warp >> 2;
    const size_t m_blk = (size_t)blockIdx.y * GBM;
    const size_t n_blk = (size_t)blockIdx.x * GBN;
    const int KT = K / GBK;

    float acc[2][8][4];
#pragma unroll
    for (int mi = 0; mi < 2; mi++)
#pragma unroll
        for (int ni = 0; ni < 8; ni++)
#pragma unroll
            for (int v = 0; v < 4; v++) acc[mi][ni][v] = 0.f;

    auto issue = [&](int kt) {
        if (kt >= KT) { cp_commit(); return; }
        const int st = kt % STAGES;
        const int k0 = kt * GBK;
        hf* dA = sm + st * STG;
        hf* dB = dA + A_PL;
        // A: 512 chunks
#pragma unroll
        for (int i = 0; i < 2; i++) {
            int ch = tid + i * 256;
            if (!TRANSA) {
                int r = ch >> 2, kc = (ch & 3) * 8;
                cp16(dA + r * ASTR + kc,
                     Ah + (m_blk + r) * (size_t)lda + k0 + kc);
            } else {
                int r = ch >> 4, c = (ch & 15) * 8;
                cp16(dA + r * BSTR + c,
                     Ah + (size_t)(k0 + r) * lda + m_blk + c);
            }
        }
        // B: 512 chunks
#pragma unroll
        for (int i = 0; i < 2; i++) {
            int ch = tid + i * 256;
            int r = ch >> 4, c = (ch & 15) * 8;
            cp16(dB + r * BSTR + c,
                 Bh + (size_t)(k0 + r) * ldb + n_blk + c);
        }
        cp_commit();
    };

    issue(0);
    issue(1);

    for (int kt = 0; kt < KT; kt++) {
        cp_wait1();
        __syncthreads();
        issue(kt + 2);

        const hf* Ahs = sm + (kt % STAGES) * STG;
        const hf* Bhs = Ahs + A_PL;

#pragma unroll
        for (int ks = 0; ks < 2; ks++) {
            const int kk = ks * 16;
            uint32_t ah[2][4];
            if (!TRANSA) {
                const int ar = lane & 15;
                const int ac = kk + (lane >> 4) * 8;
#pragma unroll
                for (int mi = 0; mi < 2; mi++)
                    ldsm4(ah[mi], Ahs + (size_t)(wm * 32 + mi * 16 + ar) * ASTR + ac);
            } else {
                const int q = lane >> 3;
                const int arow = kk + (q >> 1) * 8 + (lane & 7);
#pragma unroll
                for (int mi = 0; mi < 2; mi++) {
                    const int acol = wm * 32 + mi * 16 + (q & 1) * 8;
                    ldsm4t(ah[mi], Ahs + (size_t)arow * BSTR + acol);
                }
            }
            uint32_t bh[8][2];
            const int q = lane >> 3;
            const int br = kk + (q & 1) * 8 + (lane & 7);
#pragma unroll
            for (int nt = 0; nt < 4; nt++) {
                const int bc = wn * 64 + nt * 16 + (q >> 1) * 8;
                uint32_t r[4];
                ldsm4t(r, Bhs + (size_t)br * BSTR + bc);
                bh[2 * nt][0] = r[0]; bh[2 * nt][1] = r[1];
                bh[2 * nt + 1][0] = r[2]; bh[2 * nt + 1][1] = r[3];
            }
#pragma unroll
            for (int mi = 0; mi < 2; mi++)
#pragma unroll
                for (int ni = 0; ni < 8; ni++)
                    mma16816(acc[mi][ni], ah[mi], bh[ni]);
        }
    }

    // ---- epilogue ----
    const int g = lane >> 2, tg = lane & 3;
#pragma unroll
    for (int mi = 0; mi < 2; mi++) {
        size_t rr[2];
        rr[0] = m_blk + wm * 32 + mi * 16 + g;
        rr[1] = rr[0] + 8;
#pragma unroll
        for (int ni = 0; ni < 8; ni++) {
            size_t col = n_blk + wn * 64 + ni * 8 + tg * 2;
#pragma unroll
            for (int h = 0; h < 2; h++) {
                size_t row = rr[h];
                float x = alpha * acc[mi][ni][2 * h];
                float y = alpha * acc[mi][ni][2 * h + 1];
                if (EPI == EPI_STORE) {
                    *reinterpret_cast<float2*>(C + row * ldc + col) = make_float2(x, y);
                } else if (EPI == EPI_ADD) {
                    float2* p = reinterpret_cast<float2*>(C + row * ldc + col);
                    float2 c = *p; c.x += x; c.y += y; *p = c;
                } else if (EPI == EPI_GATED) {
                    float2* p = reinterpret_cast<float2*>(C + row * ldc + col);
                    hf2 g2 = *reinterpret_cast<const hf2*>(Gate + row * 512 + col);
                    float2 gg = __half22float2(g2);
                    float2 c = *p; c.x += gg.x * x; c.y += gg.y * y; *p = c;
                } else if (EPI == EPI_GU) {
                    if (col < 512)
                        *reinterpret_cast<hf2*>(P2h + row * (size_t)512 + col) =
                            __floats2half2_rn(sigf(x), sigf(y));
                    else
                        *reinterpret_cast<hf2*>(Ph + row * (size_t)1024 + (col - 512)) =
                            __floats2half2_rn(geluf(x), geluf(y));
                } else if (EPI == EPI_QKV) {
                    const int reg = (int)(col >> 9);
                    hf* dst = (reg == 0) ? Ph : ((reg == 1) ? P2h : P3h);
                    float a = x, b = y;
                    if (reg < 2) { a = phif(a); b = phif(b); }
                    *reinterpret_cast<hf2*>(dst + row * (size_t)512 + (col & 511)) =
                        __floats2half2_rn(a, b);
                } else if (EPI == EPI_ACC) {
                    float2* p = reinterpret_cast<float2*>(C + row * ldc + col);
                    float2 c = *p;
                    c.x = beta * c.x + x; c.y = beta * c.y + y;
                    *p = c;
                    *reinterpret_cast<hf2*>(Ph + row * (size_t)ldp + col) =
                        __floats2half2_rn(c.x, c.y);
                } else { // EPI_PLANES
                    *reinterpret_cast<hf2*>(Ph + row * (size_t)ldp + col) =
                        __floats2half2_rn(x, y);
                }
            }
        }
    }
}

// ---------------- elementwise / norm kernels ----------------
__global__ void rms_single(const float* __restrict__ x, hf* __restrict__ yh)
{
    size_t row = blockIdx.x;
    int t = threadIdx.x;
    float4 v = reinterpret_cast<const float4*>(x + row * DD)[t];
    float ss = v.x * v.x + v.y * v.y + v.z * v.z + v.w * v.w;
#pragma unroll
    for (int o = 16; o > 0; o >>= 1) ss += __shfl_xor_sync(0xffffffffu, ss, o);
    __shared__ float sb[4];
    if ((t & 31) == 0) sb[t >> 5] = ss;
    __syncthreads();
    float tot = sb[0] + sb[1] + sb[2] + sb[3];
    float r = rsqrtf(tot * (1.0f / DD) + EPSF);
    hf2* out = reinterpret_cast<hf2*>(yh + row * DD + 4 * t);
    out[0] = __floats2half2_rn(v.x * r, v.y * r);
    out[1] = __floats2half2_rn(v.z * r, v.w * r);
}

__global__ void combine_rms_single()
{
    size_t row = blockIdx.x;
    int t = threadIdx.x;
    float4 a = reinterpret_cast<const float4*>(g_state + row * DD)[t];
    float4 b = reinterpret_cast<const float4*>(g_state + (row + (size_t)BATCH * SS) * DD)[t];
    float4 v = make_float4(0.5f * (a.x + b.x), 0.5f * (a.y + b.y),
                           0.5f * (a.z + b.z), 0.5f * (a.w + b.w));
    float ss = v.x * v.x + v.y * v.y + v.z * v.z + v.w * v.w;
#pragma unroll
    for (int o = 16; o > 0; o >>= 1) ss += __shfl_xor_sync(0xffffffffu, ss, o);
    __shared__ float sb[4];
    if ((t & 31) == 0) sb[t >> 5] = ss;
    __syncthreads();
    float tot = sb[0] + sb[1] + sb[2] + sb[3];
    float r = rsqrtf(tot * (1.0f / DD) + EPSF);
    hf2* out = reinterpret_cast<hf2*>(g_cmbh + row * DD + 4 * t);
    out[0] = __floats2half2_rn(v.x * r, v.y * r);
    out[1] = __floats2half2_rn(v.z * r, v.w * r);
}

__global__ void embed_kernel(const int* __restrict__ toks, const float* __restrict__ emb)
{
    size_t row = blockIdx.x;
    int t = threadIdx.x;
    int s = (int)(row & (SS - 1));
    int vb = (int)(row >> 11);
    int b = vb & 7, v = vb >> 3;
    int tok = toks[b * SS + s];
    const float4* src = reinterpret_cast<const float4*>(
        emb + ((size_t)v * NVOCAB + tok) * DD);
    reinterpret_cast<float4*>(g_state + row * DD)[t] = src[t];
}

// pack Wgu = [Wg|Wu], Wqkv = [Wq|Wk|Wv] (row-major 512 x 1536, fp16)
__global__ void pack_w(const float* __restrict__ Wg, const float* __restrict__ Wu,
                       const float* __restrict__ Wq, const float* __restrict__ Wk,
                       const float* __restrict__ Wv)
{
    int idx = blockIdx.x * blockDim.x + threadIdx.x;
    if (idx >= DD * 1536) return;
    int r = idx / 1536, c = idx % 1536;
    float a = (c < DD) ? Wg[r * DD + c] : Wu[r * (2 * DD) + (c - DD)];
    g_wgu[idx] = __float2half_rn(a);
    float q;
    if (c < DD)            q = Wq[r * DD + c];
    else if (c < 2 * DD)   q = Wk[r * DD + (c - DD)];
    else                   q = Wv[r * DD + (c - 2 * DD)];
    g_wqkv[idx] = __float2half_rn(q);
}

__global__ void convw(const float* __restrict__ s, hf* __restrict__ h, int n)
{
    int i = blockIdx.x * blockDim.x + threadIdx.x;
    if (i < n) h[i] = __float2half_rn(s[i]);
}

__global__ void zero_accf()
{
    size_t i = (size_t)blockIdx.x * blockDim.x + threadIdx.x;
    if (i < (size_t)VB * DD * DD) g_accf[i] = 0.f;
}

// ---------------- host launch ----------------
template <typename T>
static T* sym_addr(const void* sym)
{
    void* p = nullptr;
    cudaGetSymbolAddress(&p, sym);
    return (T*)p;
}

extern "C" void kernel_launch(void* const* d_in, const int* in_sizes, int n_in,
                              void* d_out, int out_size)
{
    const int*   toks = (const int*)d_in[0];
    const float* emb  = (const float*)d_in[1];
    const float* Wg   = (const float*)d_in[2];
    const float* Wu   = (const float*)d_in[3];
    const float* Wd   = (const float*)d_in[4];
    const float* Wq   = (const float*)d_in[5];
    const float* Wk   = (const float*)d_in[6];
    const float* Wv   = (const float*)d_in[7];
    const float* Wo   = (const float*)d_in[8];
    const float* Wlm  = (const float*)d_in[9];
    float* out = (float*)d_out;

    float* state = sym_addr<float>(g_state);
    float* accf  = sym_addr<float>(g_accf);
    hf* gateh = sym_addr<hf>(g_gateh);
    hf* nh = sym_addr<hf>(g_nh);
    hf* Hh = sym_addr<hf>(g_Hh);
    hf* qh = sym_addr<hf>(g_qh);
    hf* kh = sym_addr<hf>(g_kh);
    hf* vh = sym_addr<hf>(g_vh);
    hf* acch = sym_addr<hf>(g_acch);
    hf* awh = sym_addr<hf>(g_awh);
    hf* cmbh = sym_addr<hf>(g_cmbh);
    hf* wgu = sym_addr<hf>(g_wgu);   hf* wqkv = sym_addr<hf>(g_wqkv);
    hf* wd = sym_addr<hf>(g_wd);     hf* wo = sym_addr<hf>(g_wo);
    hf* wlm = sym_addr<hf>(g_wlm);

    const int SMEM_NN = STAGES * (GBM * ASTR + GBK * BSTR) * 2;
    const int SMEM_TN = STAGES * (2 * GBK * BSTR) * 2;

    cudaFuncSetAttribute((const void*)gemm<EPI_GU,     false>, cudaFuncAttributeMaxDynamicSharedMemorySize, SMEM_NN);
    cudaFuncSetAttribute((const void*)gemm<EPI_GATED,  false>, cudaFuncAttributeMaxDynamicSharedMemorySize, SMEM_NN);
    cudaFuncSetAttribute((const void*)gemm<EPI_QKV,    false>, cudaFuncAttributeMaxDynamicSharedMemorySize, SMEM_NN);
    cudaFuncSetAttribute((const void*)gemm<EPI_ACC,    true >, cudaFuncAttributeMaxDynamicSharedMemorySize, SMEM_TN);
    cudaFuncSetAttribute((const void*)gemm<EPI_PLANES, false>, cudaFuncAttributeMaxDynamicSharedMemorySize, SMEM_NN);
    cudaFuncSetAttribute((const void*)gemm<EPI_ADD,    false>, cudaFuncAttributeMaxDynamicSharedMemorySize, SMEM_NN);
    cudaFuncSetAttribute((const void*)gemm<EPI_STORE,  false>, cudaFuncAttributeMaxDynamicSharedMemorySize, SMEM_NN);

    const float inv_s      = 1.0f / (float)SS;
    const float inv_sqrt_d = 1.0f / sqrtf((float)DD);
    const size_t tok_str = (size_t)SS * DD;
    const size_t acc_str = (size_t)DD * DD;

    embed_kernel<<<NTOK, 128>>>(toks, emb);
    pack_w<<<(DD * 1536 + 255) / 256, 256>>>(Wg, Wu, Wq, Wk, Wv);
    convw<<<(2 * DD * DD + 255) / 256, 256>>>(Wd, wd, 2 * DD * DD);
    convw<<<(DD * DD + 255) / 256, 256>>>(Wo, wo, DD * DD);
    convw<<<(DD * NVOCAB + 255) / 256, 256>>>(Wlm, wlm, DD * NVOCAB);
    zero_accf<<<(int)(((size_t)VB * DD * DD + 255) / 256), 256>>>();

    for (int step = 0; step < NSTEPS; step++) {
        rms_single<<<NTOK, 128>>>(state, nh);
        // GU = n @ [Wg|Wu]: gate=sigmoid fp16 (P2h), H=gelu fp16 (Ph)
        gemm<EPI_GU, false><<<dim3(1536 / GBN, NTOK / GBM, 1), 256, SMEM_NN>>>(
            NTOK, 1536, DD, nh, DD, 0, wgu, 1536, 0,
            1.f, 0.f, nullptr, 0, 0, Hh, 1024, 0,
            gateh, nullptr, nullptr);
        // state += gate * (H @ Wd)
        gemm<EPI_GATED, false><<<dim3(DD / GBN, NTOK / GBM, 1), 256, SMEM_NN>>>(
            NTOK, DD, 2 * DD, Hh, 2 * DD, 0, wd, DD, 0,
            1.f, 0.f, state, DD, 0, nullptr, 0, 0,
            nullptr, nullptr, gateh);
        rms_single<<<NTOK, 128>>>(state, nh);
        // QKV = n2 @ [Wq|Wk|Wv]: q=phi (Ph), k=phi (P2h), v (P3h)
        gemm<EPI_QKV, false><<<dim3(1536 / GBN, NTOK / GBM, 1), 256, SMEM_NN>>>(
            NTOK, 1536, DD, nh, DD, 0, wqkv, 1536, 0,
            1.f, 0.f, nullptr, 0, 0, qh, DD, 0,
            kh, vh, nullptr);
        // acc = DECAY*acc + inv_s * k^T @ v (batched, f32 master); acc hi plane
        gemm<EPI_ACC, true><<<dim3(DD / GBN, DD / GBM, VB), 256, SMEM_TN>>>(
            DD, DD, SS, kh, DD, tok_str, vh, DD, tok_str,
            inv_s, DECAYF, accf, DD, acc_str, acch, DD, acc_str,
            nullptr, nullptr, nullptr);
        // accWo = acc @ Wo -> fp16 plane (batched)
        gemm<EPI_PLANES, false><<<dim3(DD / GBN, DD / GBM, VB), 256, SMEM_NN>>>(
            DD, DD, DD, acch, DD, acc_str, wo, DD, 0,
            1.f, 0.f, nullptr, 0, 0, awh, DD, acc_str,
            nullptr, nullptr, nullptr);
        // state += inv_sqrt_d * q @ accWo (batched)
        gemm<EPI_ADD, false><<<dim3(DD / GBN, SS / GBM, VB), 256, SMEM_NN>>>(
            SS, DD, DD, qh, DD, tok_str, awh, DD, acc_str,
            inv_sqrt_d, 0.f, state, DD, tok_str, nullptr, 0, 0,
            nullptr, nullptr, nullptr);
    }

    combine_rms_single<<<BATCH * SS, 128>>>();
    gemm<EPI_STORE, false><<<dim3(NVOCAB / GBN, (BATCH * SS) / GBM, 1), 256, SMEM_NN>>>(
        BATCH * SS, NVOCAB, DD, cmbh, DD, 0, wlm, NVOCAB, 0,
        1.f, 0.f, out, NVOCAB, 0, nullptr, 0, 0,
        nullptr, nullptr, nullptr);
    (void)in_sizes; (void)n_in; (void)out_size;
}

// round 10
// speedup vs baseline: 5.7987x; 1.0007x over previous
#include <cuda_runtime.h>
#include <cuda_fp16.h>
#include <math.h>
#include <stdint.h>

// ---------------- problem constants ----------------
#define DD     512
#define SS     2048
#define BATCH  8
#define VB     16
#define NTOK   32768
#define NVOCAB 8192
#define NSTEPS 16
#define DECAYF 0.999f
#define EPSF   1e-6f

typedef __half hf;
typedef __half2 hf2;

// ---------------- scratch (static device globals; allocation-free) ----------------
__device__ float g_state[(size_t)NTOK * DD];
__device__ float g_accf [(size_t)VB * DD * DD];           // f32 master accumulator

__device__ hf g_gateh[(size_t)NTOK * DD];                 // sigmoid gate (fp16)
__device__ hf g_nh[(size_t)NTOK * DD];                    // rms(state)
__device__ hf g_Hh[(size_t)NTOK * 2 * DD];                // gelu H
__device__ hf g_qh[(size_t)NTOK * DD];                    // phi(q)
__device__ hf g_kh[(size_t)NTOK * DD];                    // phi(k)
__device__ hf g_vh[(size_t)NTOK * DD];                    // v
__device__ hf g_acch[(size_t)VB * DD * DD];               // acc fp16 plane
__device__ hf g_awh [(size_t)VB * DD * DD];               // accWo
__device__ hf g_cmbh[(size_t)BATCH * SS * DD];            // combined

// weights (fp16, B side)
__device__ hf g_wgu [DD * 1536];
__device__ hf g_wqkv[DD * 1536];
__device__ hf g_wd  [2 * DD * DD];
__device__ hf g_wo  [DD * DD];
__device__ hf g_wlm [DD * NVOCAB];

// ---------------- helpers ----------------
__device__ __forceinline__ float sigf(float x) { return 1.0f / (1.0f + expf(-x)); }
__device__ __forceinline__ float geluf(float x)
{ return 0.5f * x * (1.0f + erff(x * 0.70710678118654752f)); }
__device__ __forceinline__ float phif(float x) { return (x > 0.f) ? x + 1.f : expf(x); }

__device__ __forceinline__ void cp16(void* dst, const void* src)
{
    uint32_t d = (uint32_t)__cvta_generic_to_shared(dst);
    asm volatile("cp.async.cg.shared.global [%0], [%1], 16;" :: "r"(d), "l"(src));
}
__device__ __forceinline__ void cp_commit() { asm volatile("cp.async.commit_group;" ::: "memory"); }
__device__ __forceinline__ void cp_wait1()  { asm volatile("cp.async.wait_group 1;" ::: "memory"); }

__device__ __forceinline__ void ldsm4(uint32_t r[4], const void* p)
{
    uint32_t a = (uint32_t)__cvta_generic_to_shared(p);
    asm volatile("ldmatrix.sync.aligned.m8n8.x4.shared.b16 {%0,%1,%2,%3}, [%4];"
                 : "=r"(r[0]), "=r"(r[1]), "=r"(r[2]), "=r"(r[3]) : "r"(a));
}
__device__ __forceinline__ void ldsm4t(uint32_t r[4], const void* p)
{
    uint32_t a = (uint32_t)__cvta_generic_to_shared(p);
    asm volatile("ldmatrix.sync.aligned.m8n8.x4.trans.shared.b16 {%0,%1,%2,%3}, [%4];"
                 : "=r"(r[0]), "=r"(r[1]), "=r"(r[2]), "=r"(r[3]) : "r"(a));
}
__device__ __forceinline__ void mma16816(float c[4], const uint32_t a[4], const uint32_t b[2])
{
    asm volatile(
        "mma.sync.aligned.m16n8k16.row.col.f32.f16.f16.f32 "
        "{%0,%1,%2,%3}, {%4,%5,%6,%7}, {%8,%9}, {%0,%1,%2,%3};"
        : "+f"(c[0]), "+f"(c[1]), "+f"(c[2]), "+f"(c[3])
        : "r"(a[0]), "r"(a[1]), "r"(a[2]), "r"(a[3]), "r"(b[0]), "r"(b[1]));
}

// ---------------- pipelined fp16 tensor-core GEMM ----------------
// GBK=64; MB = 128 or 64 (block M-tile). N-tile fixed 128.
#define GBN 128
#define GBK 64
#define ASTR 72     // smem A row stride (64 + 8 pad)
#define BSTR 136    // smem row stride for [k][n] / [k][m]
#define STAGES 3

enum { EPI_STORE = 0, EPI_GU = 1, EPI_GATED = 2, EPI_QKV = 3,
       EPI_ACC = 4, EPI_PLANES = 5, EPI_ADD = 6 };

template <int EPI, bool TRANSA, int MB>
__global__ void __launch_bounds__(256, 2) gemm(
    int M, int N, int K,
    const hf* __restrict__ Ah, int lda, size_t sA,
    const hf* __restrict__ Bh, int ldb, size_t sB,
    float alpha, float beta,
    float* __restrict__ C, int ldc, size_t sC,
    hf* __restrict__ Ph, int ldp, size_t sP,
    hf* __restrict__ P2h, hf* __restrict__ P3h,
    const hf* __restrict__ Gate)
{
    const int z = blockIdx.z;
    Ah += (size_t)z * sA;
    Bh += (size_t)z * sB;
    if (C)  C  += (size_t)z * sC;
    if (Ph) Ph += (size_t)z * sP;

    constexpr int A_PL = TRANSA ? (GBK * BSTR) : (MB * ASTR);
    constexpr int B_PL = GBK * BSTR;
    constexpr int STG  = A_PL + B_PL;
    // warp layout
    constexpr int WMASK = (MB == 128) ? 3 : 1;   // warps along M - 1
    constexpr int WNSH  = (MB == 128) ? 2 : 1;   // warp>>WNSH = wn
    constexpr int WCOLS = (MB == 128) ? 64 : 32; // cols per warp
    constexpr int NI    = WCOLS / 8;
    constexpr int A_ITERS = (TRANSA ? 1024 : MB * 8) / 256;

    extern __shared__ __align__(16) hf sm[];

    const int tid = threadIdx.x, lane = tid & 31, warp = tid >> 5;
    const int wm = warp & WMASK, wn = warp >> WNSH;
    const size_t m_blk = (size_t)blockIdx.y * MB;
    const size_t n_blk = (size_t)blockIdx.x * GBN;
    const int KT = K / GBK;

    float acc[2][NI][4];
#pragma unroll
    for (int mi = 0; mi < 2; mi++)
#pragma unroll
        for (int ni = 0; ni < NI; ni++)
#pragma unroll
            for (int v = 0; v < 4; v++) acc[mi][ni][v] = 0.f;

    auto issue = [&](int kt) {
        if (kt >= KT) { cp_commit(); return; }
        const int st = kt % STAGES;
        const int k0 = kt * GBK;
        hf* dA = sm + st * STG;
        hf* dB = dA + A_PL;
#pragma unroll
        for (int i = 0; i < A_ITERS; i++) {
            int ch = tid + i * 256;
            if (!TRANSA) {
                int r = ch >> 3, kc = (ch & 7) * 8;
                cp16(dA + r * ASTR + kc,
                     Ah + (m_blk + r) * (size_t)lda + k0 + kc);
            } else {
                int r = ch >> 4, c = (ch & 15) * 8;
                cp16(dA + r * BSTR + c,
                     Ah + (size_t)(k0 + r) * lda + m_blk + c);
            }
        }
#pragma unroll
        for (int i = 0; i < 4; i++) {
            int ch = tid + i * 256;
            int r = ch >> 4, c = (ch & 15) * 8;
            cp16(dB + r * BSTR + c,
                 Bh + (size_t)(k0 + r) * ldb + n_blk + c);
        }
        cp_commit();
    };

    issue(0);
    issue(1);

    for (int kt = 0; kt < KT; kt++) {
        cp_wait1();
        __syncthreads();
        issue(kt + 2);

        const hf* Ahs = sm + (kt % STAGES) * STG;
        const hf* Bhs = Ahs + A_PL;

#pragma unroll
        for (int ks = 0; ks < 4; ks++) {
            const int kk = ks * 16;
            uint32_t ah[2][4];
            if (!TRANSA) {
                const int ar = lane & 15;
                const int ac = kk + (lane >> 4) * 8;
#pragma unroll
                for (int mi = 0; mi < 2; mi++)
                    ldsm4(ah[mi], Ahs + (size_t)(wm * 32 + mi * 16 + ar) * ASTR + ac);
            } else {
                const int q = lane >> 3;
                const int arow = kk + (q >> 1) * 8 + (lane & 7);
#pragma unroll
                for (int mi = 0; mi < 2; mi++) {
                    const int acol = wm * 32 + mi * 16 + (q & 1) * 8;
                    ldsm4t(ah[mi], Ahs + (size_t)arow * BSTR + acol);
                }
            }
            uint32_t bh[NI][2];
            const int q = lane >> 3;
            const int br = kk + (q & 1) * 8 + (lane & 7);
#pragma unroll
            for (int nt = 0; nt < NI / 2; nt++) {
                const int bc = wn * WCOLS + nt * 16 + (q >> 1) * 8;
                uint32_t r[4];
                ldsm4t(r, Bhs + (size_t)br * BSTR + bc);
                bh[2 * nt][0] = r[0]; bh[2 * nt][1] = r[1];
                bh[2 * nt + 1][0] = r[2]; bh[2 * nt + 1][1] = r[3];
            }
#pragma unroll
            for (int mi = 0; mi < 2; mi++)
#pragma unroll
                for (int ni = 0; ni < NI; ni++)
                    mma16816(acc[mi][ni], ah[mi], bh[ni]);
        }
    }

    // ---- epilogue ----
    const int g = lane >> 2, tg = lane & 3;
#pragma unroll
    for (int mi = 0; mi < 2; mi++) {
        size_t rr[2];
        rr[0] = m_blk + wm * 32 + mi * 16 + g;
        rr[1] = rr[0] + 8;
#pragma unroll
        for (int ni = 0; ni < NI; ni++) {
            size_t col = n_blk + wn * WCOLS + ni * 8 + tg * 2;
#pragma unroll
            for (int h = 0; h < 2; h++) {
                size_t row = rr[h];
                float x = alpha * acc[mi][ni][2 * h];
                float y = alpha * acc[mi][ni][2 * h + 1];
                if (EPI == EPI_STORE) {
                    *reinterpret_cast<float2*>(C + row * ldc + col) = make_float2(x, y);
                } else if (EPI == EPI_ADD) {
                    float2* p = reinterpret_cast<float2*>(C + row * ldc + col);
                    float2 c = *p; c.x += x; c.y += y; *p = c;
                } else if (EPI == EPI_GATED) {
                    float2* p = reinterpret_cast<float2*>(C + row * ldc + col);
                    hf2 g2 = *reinterpret_cast<const hf2*>(Gate + row * 512 + col);
                    float2 gg = __half22float2(g2);
                    float2 c = *p; c.x += gg.x * x; c.y += gg.y * y; *p = c;
                } else if (EPI == EPI_GU) {
                    if (col < 512)
                        *reinterpret_cast<hf2*>(P2h + row * (size_t)512 + col) =
                            __floats2half2_rn(sigf(x), sigf(y));
                    else
                        *reinterpret_cast<hf2*>(Ph + row * (size_t)1024 + (col - 512)) =
                            __floats2half2_rn(geluf(x), geluf(y));
                } else if (EPI == EPI_QKV) {
                    const int reg = (int)(col >> 9);
                    hf* dst = (reg == 0) ? Ph : ((reg == 1) ? P2h : P3h);
                    float a = x, b = y;
                    if (reg < 2) { a = phif(a); b = phif(b); }
                    *reinterpret_cast<hf2*>(dst + row * (size_t)512 + (col & 511)) =
                        __floats2half2_rn(a, b);
                } else if (EPI == EPI_ACC) {
                    float2* p = reinterpret_cast<float2*>(C + row * ldc + col);
                    float2 c = *p;
                    c.x = beta * c.x + x; c.y = beta * c.y + y;
                    *p = c;
                    *reinterpret_cast<hf2*>(Ph + row * (size_t)ldp + col) =
                        __floats2half2_rn(c.x, c.y);
                } else { // EPI_PLANES
                    *reinterpret_cast<hf2*>(Ph + row * (size_t)ldp + col) =
                        __floats2half2_rn(x, y);
                }
            }
        }
    }
}

// ---------------- elementwise / norm kernels (warp-per-row) ----------------
__global__ void rms_single(const float* __restrict__ x, hf* __restrict__ yh)
{
    const int lane = threadIdx.x & 31;
    const size_t row = (size_t)blockIdx.x * 8 + (threadIdx.x >> 5);
    const float4* xr = reinterpret_cast<const float4*>(x + row * DD);
    float4 v[4];
    float ss = 0.f;
#pragma unroll
    for (int i = 0; i < 4; i++) {
        v[i] = xr[lane + 32 * i];
        ss += v[i].x * v[i].x + v[i].y * v[i].y + v[i].z * v[i].z + v[i].w * v[i].w;
    }
#pragma unroll
    for (int o = 16; o > 0; o >>= 1) ss += __shfl_xor_sync(0xffffffffu, ss, o);
    float r = rsqrtf(ss * (1.0f / DD) + EPSF);
    hf2* out = reinterpret_cast<hf2*>(yh + row * DD);
#pragma unroll
    for (int i = 0; i < 4; i++) {
        out[(lane + 32 * i) * 2]     = __floats2half2_rn(v[i].x * r, v[i].y * r);
        out[(lane + 32 * i) * 2 + 1] = __floats2half2_rn(v[i].z * r, v[i].w * r);
    }
}

__global__ void combine_rms_single()
{
    const int lane = threadIdx.x & 31;
    const size_t row = (size_t)blockIdx.x * 8 + (threadIdx.x >> 5);
    const float4* ar = reinterpret_cast<const float4*>(g_state + row * DD);
    const float4* br = reinterpret_cast<const float4*>(
        g_state + (row + (size_t)BATCH * SS) * DD);
    float4 v[4];
    float ss = 0.f;
#pragma unroll
    for (int i = 0; i < 4; i++) {
        float4 a = ar[lane + 32 * i], b = br[lane + 32 * i];
        v[i] = make_float4(0.5f * (a.x + b.x), 0.5f * (a.y + b.y),
                           0.5f * (a.z + b.z), 0.5f * (a.w + b.w));
        ss += v[i].x * v[i].x + v[i].y * v[i].y + v[i].z * v[i].z + v[i].w * v[i].w;
    }
#pragma unroll
    for (int o = 16; o > 0; o >>= 1) ss += __shfl_xor_sync(0xffffffffu, ss, o);
    float r = rsqrtf(ss * (1.0f / DD) + EPSF);
    hf2* out = reinterpret_cast<hf2*>(g_cmbh + row * DD);
#pragma unroll
    for (int i = 0; i < 4; i++) {
        out[(lane + 32 * i) * 2]     = __floats2half2_rn(v[i].x * r, v[i].y * r);
        out[(lane + 32 * i) * 2 + 1] = __floats2half2_rn(v[i].z * r, v[i].w * r);
    }
}

__global__ void embed_kernel(const int* __restrict__ toks, const float* __restrict__ emb)
{
    size_t row = blockIdx.x;
    int t = threadIdx.x;
    int s = (int)(row & (SS - 1));
    int vb = (int)(row >> 11);
    int b = vb & 7, v = vb >> 3;
    int tok = toks[b * SS + s];
    const float4* src = reinterpret_cast<const float4*>(
        emb + ((size_t)v * NVOCAB + tok) * DD);
    reinterpret_cast<float4*>(g_state + row * DD)[t] = src[t];
}

__global__ void pack_w(const float* __restrict__ Wg, const float* __restrict__ Wu,
                       const float* __restrict__ Wq, const float* __restrict__ Wk,
                       const float* __restrict__ Wv)
{
    int idx = blockIdx.x * blockDim.x + threadIdx.x;
    if (idx >= DD * 1536) return;
    int r = idx / 1536, c = idx % 1536;
    float a = (c < DD) ? Wg[r * DD + c] : Wu[r * (2 * DD) + (c - DD)];
    g_wgu[idx] = __float2half_rn(a);
    float q;
    if (c < DD)            q = Wq[r * DD + c];
    else if (c < 2 * DD)   q = Wk[r * DD + (c - DD)];
    else                   q = Wv[r * DD + (c - 2 * DD)];
    g_wqkv[idx] = __float2half_rn(q);
}

__global__ void convw(const float* __restrict__ s, hf* __restrict__ h, int n)
{
    int i = blockIdx.x * blockDim.x + threadIdx.x;
    if (i < n) h[i] = __float2half_rn(s[i]);
}

__global__ void zero_accf()
{
    size_t i = (size_t)blockIdx.x * blockDim.x + threadIdx.x;
    if (i < (size_t)VB * DD * DD) g_accf[i] = 0.f;
}

// ---------------- host launch ----------------
template <typename T>
static T* sym_addr(const void* sym)
{
    void* p = nullptr;
    cudaGetSymbolAddress(&p, sym);
    return (T*)p;
}

extern "C" void kernel_launch(void* const* d_in, const int* in_sizes, int n_in,
                              void* d_out, int out_size)
{
    const int*   toks = (const int*)d_in[0];
    const float* emb  = (const float*)d_in[1];
    const float* Wg   = (const float*)d_in[2];
    const float* Wu   = (const float*)d_in[3];
    const float* Wd   = (const float*)d_in[4];
    const float* Wq   = (const float*)d_in[5];
    const float* Wk   = (const float*)d_in[6];
    const float* Wv   = (const float*)d_in[7];
    const float* Wo   = (const float*)d_in[8];
    const float* Wlm  = (const float*)d_in[9];
    float* out = (float*)d_out;

    float* state = sym_addr<float>(g_state);
    float* accf  = sym_addr<float>(g_accf);
    hf* gateh = sym_addr<hf>(g_gateh);
    hf* nh = sym_addr<hf>(g_nh);
    hf* Hh = sym_addr<hf>(g_Hh);
    hf* qh = sym_addr<hf>(g_qh);
    hf* kh = sym_addr<hf>(g_kh);
    hf* vh = sym_addr<hf>(g_vh);
    hf* acch = sym_addr<hf>(g_acch);
    hf* awh = sym_addr<hf>(g_awh);
    hf* cmbh = sym_addr<hf>(g_cmbh);
    hf* wgu = sym_addr<hf>(g_wgu);   hf* wqkv = sym_addr<hf>(g_wqkv);
    hf* wd = sym_addr<hf>(g_wd);     hf* wo = sym_addr<hf>(g_wo);
    hf* wlm = sym_addr<hf>(g_wlm);

    const int SMEM_128 = STAGES * (128 * ASTR + GBK * BSTR) * 2;   // 107,520
    const int SMEM_64  = STAGES * (64  * ASTR + GBK * BSTR) * 2;   //  79,872
    const int SMEM_TN  = STAGES * (2 * GBK * BSTR) * 2;            // 104,448

    cudaFuncSetAttribute((const void*)gemm<EPI_GU,     false, 128>, cudaFuncAttributeMaxDynamicSharedMemorySize, SMEM_128);
    cudaFuncSetAttribute((const void*)gemm<EPI_GATED,  false, 64 >, cudaFuncAttributeMaxDynamicSharedMemorySize, SMEM_64);
    cudaFuncSetAttribute((const void*)gemm<EPI_QKV,    false, 128>, cudaFuncAttributeMaxDynamicSharedMemorySize, SMEM_128);
    cudaFuncSetAttribute((const void*)gemm<EPI_ACC,    true,  128>, cudaFuncAttributeMaxDynamicSharedMemorySize, SMEM_TN);
    cudaFuncSetAttribute((const void*)gemm<EPI_PLANES, false, 128>, cudaFuncAttributeMaxDynamicSharedMemorySize, SMEM_128);
    cudaFuncSetAttribute((const void*)gemm<EPI_ADD,    false, 64 >, cudaFuncAttributeMaxDynamicSharedMemorySize, SMEM_64);
    cudaFuncSetAttribute((const void*)gemm<EPI_STORE,  false, 128>, cudaFuncAttributeMaxDynamicSharedMemorySize, SMEM_128);

    const float inv_s      = 1.0f / (float)SS;
    const float inv_sqrt_d = 1.0f / sqrtf((float)DD);
    const size_t tok_str = (size_t)SS * DD;
    const size_t acc_str = (size_t)DD * DD;

    embed_kernel<<<NTOK, 128>>>(toks, emb);
    pack_w<<<(DD * 1536 + 255) / 256, 256>>>(Wg, Wu, Wq, Wk, Wv);
    convw<<<(2 * DD * DD + 255) / 256, 256>>>(Wd, wd, 2 * DD * DD);
    convw<<<(DD * DD + 255) / 256, 256>>>(Wo, wo, DD * DD);
    convw<<<(DD * NVOCAB + 255) / 256, 256>>>(Wlm, wlm, DD * NVOCAB);
    zero_accf<<<(int)(((size_t)VB * DD * DD + 255) / 256), 256>>>();

    for (int step = 0; step < NSTEPS; step++) {
        rms_single<<<NTOK / 8, 256>>>(state, nh);
        // GU = n @ [Wg|Wu]: gate=sigmoid fp16 (P2h), H=gelu fp16 (Ph)
        gemm<EPI_GU, false, 128><<<dim3(1536 / GBN, NTOK / 128, 1), 256, SMEM_128>>>(
            NTOK, 1536, DD, nh, DD, 0, wgu, 1536, 0,
            1.f, 0.f, nullptr, 0, 0, Hh, 1024, 0,
            gateh, nullptr, nullptr);
        // state += gate * (H @ Wd)   (M64 tile: 2048 blocks)
        gemm<EPI_GATED, false, 64><<<dim3(DD / GBN, NTOK / 64, 1), 256, SMEM_64>>>(
            NTOK, DD, 2 * DD, Hh, 2 * DD, 0, wd, DD, 0,
            1.f, 0.f, state, DD, 0, nullptr, 0, 0,
            nullptr, nullptr, gateh);
        rms_single<<<NTOK / 8, 256>>>(state, nh);
        // QKV = n2 @ [Wq|Wk|Wv]: q=phi (Ph), k=phi (P2h), v (P3h)
        gemm<EPI_QKV, false, 128><<<dim3(1536 / GBN, NTOK / 128, 1), 256, SMEM_128>>>(
            NTOK, 1536, DD, nh, DD, 0, wqkv, 1536, 0,
            1.f, 0.f, nullptr, 0, 0, qh, DD, 0,
            kh, vh, nullptr);
        // acc = DECAY*acc + inv_s * k^T @ v (batched, f32 master); acc fp16 plane
        gemm<EPI_ACC, true, 128><<<dim3(DD / GBN, DD / 128, VB), 256, SMEM_TN>>>(
            DD, DD, SS, kh, DD, tok_str, vh, DD, tok_str,
            inv_s, DECAYF, accf, DD, acc_str, acch, DD, acc_str,
            nullptr, nullptr, nullptr);
        // accWo = acc @ Wo -> fp16 plane (batched)
        gemm<EPI_PLANES, false, 128><<<dim3(DD / GBN, DD / 128, VB), 256, SMEM_128>>>(
            DD, DD, DD, acch, DD, acc_str, wo, DD, 0,
            1.f, 0.f, nullptr, 0, 0, awh, DD, acc_str,
            nullptr, nullptr, nullptr);
        // state += inv_sqrt_d * q @ accWo (batched, M64 tile: 2048 blocks)
        gemm<EPI_ADD, false, 64><<<dim3(DD / GBN, SS / 64, VB), 256, SMEM_64>>>(
            SS, DD, DD, qh, DD, tok_str, awh, DD, acc_str,
            inv_sqrt_d, 0.f, state, DD, tok_str, nullptr, 0, 0,
            nullptr, nullptr, nullptr);
    }

    combine_rms_single<<<BATCH * SS / 8, 256>>>();
    gemm<EPI_STORE, false, 128><<<dim3(NVOCAB / GBN, (BATCH * SS) / 128, 1), 256, SMEM_128>>>(
        BATCH * SS, NVOCAB, DD, cmbh, DD, 0, wlm, NVOCAB, 0,
        1.f, 0.f, out, NVOCAB, 0, nullptr, 0, 0,
        nullptr, nullptr, nullptr);
    (void)in_sizes; (void)n_in; (void)out_size;
}